// round 1
// baseline (speedup 1.0000x reference)
#include <cuda_runtime.h>
#include <math.h>

#define NB 8
#define NT 12
#define NN 1024
#define ND 64
#define NE 64
#define NM 16
#define ROWS_TOT (NB*NT*NN)      // 98304

// ---------------- scratch (device globals; allocation-free rule) ----------
__device__ float g_phiK[NM*NE];          // [m][e]
__device__ float g_V[NM*ND];             // [m][d]
__device__ float g_KtV[NE*ND];           // [e][d]
__device__ float g_dinv[NN];
__device__ float g_mv[NB*NN*ND];         // mean over t of mem_val
__device__ float g_Hp[ROWS_TOT*ND];      // H_prime
__device__ float g_X1[ROWS_TOT*ND];
__device__ float g_X2[ROWS_TOT*ND];

// ---------------- small precompute ----------------------------------------
__global__ void k_pre(const float* __restrict__ PHI, const float* __restrict__ WK,
                      const float* __restrict__ WV) {
    __shared__ float sK[NM*NE];
    __shared__ float sV[NM*ND];
    int t = threadIdx.x;
    for (int i = t; i < NM*NE; i += 256) {
        int m = i >> 6, de = i & 63;
        float s = 0.f, sv = 0.f;
        for (int j = 0; j < NE; j++) {
            float p = PHI[m*NE + j];
            s  += p * WK[de*NE + j];   // K[m,e]  = sum_j PHI[m,j] WK[e,j]
            sv += p * WV[de*NE + j];   // V[m,d]  = sum_j PHI[m,j] WV[d,j]
        }
        float pk = (s > 0.f) ? s + 1.f : expf(s);   // elu+1
        sK[i] = pk; g_phiK[i] = pk;
        sV[i] = sv; g_V[i] = sv;
    }
    __syncthreads();
    for (int i = t; i < NE*ND; i += 256) {
        int e = i >> 6, d = i & 63;
        float s = 0.f;
        #pragma unroll
        for (int m = 0; m < NM; m++) s += sK[m*NE + e] * sV[m*ND + d];
        g_KtV[i] = s;
    }
}

__global__ void k_deg(const float* __restrict__ A) {
    __shared__ float red[256];
    int n = blockIdx.x, t = threadIdx.x;
    float s = 0.f;
    for (int j = t; j < NN; j += 256) s += A[(size_t)n*NN + j];
    red[t] = s; __syncthreads();
    for (int o = 128; o > 0; o >>= 1) { if (t < o) red[t] += red[t+o]; __syncthreads(); }
    if (t == 0) g_dinv[n] = rsqrtf(red[0] + 1e-12f);
}

__global__ void k_zero() {
    int i = blockIdx.x*256 + threadIdx.x;
    if (i < NB*NN*ND) g_mv[i] = 0.f;
}

// ---------------- shared-tile fp32 GEMM microkernel ------------------------
// C[64x64] += A[64x64] * B[64x64]; As row-major pitch 68, Bs K-major pitch 68.
__device__ __forceinline__ void gemm_tile(const float* __restrict__ As,
                                          const float* __restrict__ Bs,
                                          float acc[4][4], int ty, int tx) {
    #pragma unroll 4
    for (int kk = 0; kk < 64; kk++) {
        float a0 = As[(ty*4+0)*68 + kk];
        float a1 = As[(ty*4+1)*68 + kk];
        float a2 = As[(ty*4+2)*68 + kk];
        float a3 = As[(ty*4+3)*68 + kk];
        float4 b4 = *(const float4*)(Bs + kk*68 + tx*4);
        acc[0][0] += a0*b4.x; acc[0][1] += a0*b4.y; acc[0][2] += a0*b4.z; acc[0][3] += a0*b4.w;
        acc[1][0] += a1*b4.x; acc[1][1] += a1*b4.y; acc[1][2] += a1*b4.z; acc[1][3] += a1*b4.w;
        acc[2][0] += a2*b4.x; acc[2][1] += a2*b4.y; acc[2][2] += a2*b4.z; acc[2][3] += a2*b4.w;
        acc[3][0] += a3*b4.x; acc[3][1] += a3*b4.y; acc[3][2] += a3*b4.z; acc[3][3] += a3*b4.w;
    }
}

// ---------------- fused attention + out proj + LN (64-row tiles) -----------
// dyn smem layout (floats): Hs[64*68] Ps[64*68] Bs[64*68] QKs[64*20]
//                           phiKs[1024] Vs[1024] rmean[64] rinv[64]
#define SMEM_ATTN ((3*64*68 + 64*20 + 1024 + 1024 + 128) * 4)

__global__ void k_attn(const float* __restrict__ H, const float* __restrict__ WQ,
                       const float* __restrict__ outW, const float* __restrict__ outb,
                       const float* __restrict__ lng, const float* __restrict__ lnb) {
    extern __shared__ __align__(16) float sm[];
    float* Hs    = sm;
    float* Ps    = Hs + 64*68;
    float* Bs    = Ps + 64*68;
    float* QKs   = Bs + 64*68;
    float* phiKs = QKs + 64*20;
    float* Vs    = phiKs + 1024;
    float* rmean = Vs + 1024;
    float* rinv  = rmean + 64;

    int tid = threadIdx.x;
    int tx = tid & 15, ty = tid >> 4;
    int row0 = blockIdx.x * 64;
    const float* Hb = H + (size_t)row0 * 64;

    for (int l = tid; l < 4096; l += 256) {
        int r = l >> 6, c = l & 63;
        Hs[r*68 + c] = Hb[l];
        Bs[c*68 + r] = WQ[l];              // Bs[k][e] = WQ[e,k]
    }
    for (int l = tid; l < 1024; l += 256) { phiKs[l] = g_phiK[l]; Vs[l] = g_V[l]; }
    __syncthreads();

    // GEMM1: Q = H * WQ^T, then phiQ = elu(Q)+1 -> Ps
    {
        float acc[4][4] = {};
        gemm_tile(Hs, Bs, acc, ty, tx);
        #pragma unroll
        for (int i = 0; i < 4; i++)
            #pragma unroll
            for (int j = 0; j < 4; j++) {
                float q = acc[i][j];
                Ps[(ty*4+i)*68 + tx*4+j] = (q > 0.f) ? q + 1.f : expf(q);
            }
    }
    __syncthreads();

    // QK[r][m] = (phiQ[r] . phiK[m]) / 8
    {
        int r = tid >> 2, mg = tid & 3;
        #pragma unroll
        for (int mm = 0; mm < 4; mm++) {
            int m = mg*4 + mm;
            float s = 0.f;
            for (int e = 0; e < 64; e++) s += Ps[r*68 + e] * phiKs[m*64 + e];
            QKs[r*20 + m] = s * 0.125f;
        }
    }
    __syncthreads();

    // softmax over M=16 per row
    if (tid < 64) {
        float mx = -1e30f;
        #pragma unroll
        for (int m = 0; m < 16; m++) mx = fmaxf(mx, QKs[tid*20 + m]);
        float s = 0.f;
        #pragma unroll
        for (int m = 0; m < 16; m++) { float e_ = expf(QKs[tid*20 + m] - mx); QKs[tid*20 + m] = e_; s += e_; }
        float inv = 1.f / s;
        #pragma unroll
        for (int m = 0; m < 16; m++) QKs[tid*20 + m] *= inv;
    }
    // reload Bs with KtV (safe: GEMM1 done before previous sync)
    for (int l = tid; l < 4096; l += 256)
        Bs[(l >> 6)*68 + (l & 63)] = g_KtV[l];    // Bs[e][d]
    __syncthreads();

    // mem_val -> mv (mean over t via atomic)
    {
        int r = tid >> 2, dq = tid & 3;
        int grow = row0 + r;
        int b_ = grow / (NT*NN);
        int n_ = grow & (NN - 1);
        float am[16];
        #pragma unroll
        for (int m = 0; m < 16; m++) am[m] = QKs[r*20 + m];
        float* mvp = g_mv + ((size_t)(b_*NN + n_))*64 + dq*16;
        #pragma unroll
        for (int dd = 0; dd < 16; dd++) {
            float s = 0.f;
            #pragma unroll
            for (int m = 0; m < 16; m++) s += am[m] * Vs[m*64 + dq*16 + dd];
            atomicAdd(mvp + dd, s * (1.f/NT));
        }
    }

    // GEMM2: main_att = phiQ * KtV ; Hp = main_att + H  (into Hs)
    {
        float acc[4][4] = {};
        gemm_tile(Ps, Bs, acc, ty, tx);
        #pragma unroll
        for (int i = 0; i < 4; i++)
            #pragma unroll
            for (int j = 0; j < 4; j++) {
                int pos = (ty*4+i)*68 + tx*4+j;
                Hs[pos] += acc[i][j];
            }
    }
    __syncthreads();
    for (int l = tid; l < 4096; l += 256) {
        int o = l >> 6, kk = l & 63;
        Bs[kk*68 + o] = outW[l];                  // Bs[k][o] = outW[o,k]
    }
    __syncthreads();

    // GEMM3: out = Hp * outW^T + outb -> Ps
    {
        float acc[4][4] = {};
        gemm_tile(Hs, Bs, acc, ty, tx);
        #pragma unroll
        for (int i = 0; i < 4; i++)
            #pragma unroll
            for (int j = 0; j < 4; j++) {
                int c = tx*4+j;
                Ps[(ty*4+i)*68 + c] = acc[i][j] + outb[c];
            }
    }
    __syncthreads();

    if (tid < 64) {
        float s = 0.f;
        for (int c = 0; c < 64; c++) s += Ps[tid*68 + c];
        float mu = s * (1.f/64.f);
        float v = 0.f;
        for (int c = 0; c < 64; c++) { float d_ = Ps[tid*68 + c] - mu; v += d_*d_; }
        rmean[tid] = mu;
        rinv[tid]  = rsqrtf(v*(1.f/64.f) + 1e-5f);
    }
    __syncthreads();
    #pragma unroll
    for (int i = 0; i < 4; i++)
        #pragma unroll
        for (int j = 0; j < 4; j++) {
            int r = ty*4+i, c = tx*4+j;
            float v = (Ps[r*68 + c] - rmean[r]) * rinv[r] * lng[c] + lnb[c];
            g_Hp[(size_t)(row0 + r)*64 + c] = v;
        }
}

// ---------------- A_dynamic logits: S = mv . mv^T / 8 ----------------------
__global__ void k_mvS(float* __restrict__ Sout) {
    __shared__ __align__(16) float Ai[64*68];
    __shared__ __align__(16) float Bt[64*68];
    int tid = threadIdx.x, tx = tid & 15, ty = tid >> 4;
    int i0 = blockIdx.x*64, j0 = blockIdx.y*64, b = blockIdx.z;
    const float* mvb = g_mv + (size_t)b*NN*64;
    for (int l = tid; l < 4096; l += 256) {
        int r = l >> 6, d = l & 63;
        Ai[r*68 + d] = mvb[(size_t)(i0 + r)*64 + d];
        Bt[d*68 + r] = mvb[(size_t)(j0 + r)*64 + d];   // Bt[d][j]
    }
    __syncthreads();
    float acc[4][4] = {};
    gemm_tile(Ai, Bt, acc, ty, tx);
    float* Sp = Sout + (size_t)b*NN*NN;
    #pragma unroll
    for (int i = 0; i < 4; i++)
        #pragma unroll
        for (int j = 0; j < 4; j++)
            Sp[(size_t)(i0 + ty*4+i)*NN + j0 + tx*4+j] = acc[i][j] * 0.125f;
}

// ---------------- in-place softmax + fuse ---------------------------------
__global__ void k_softfuse(float* __restrict__ Adyn, float* __restrict__ Afus,
                           const float* __restrict__ Ast, const float* __restrict__ beta) {
    __shared__ float red[256];
    int n = blockIdx.x, b = blockIdx.y, t = threadIdx.x;
    float* Sr = Adyn + ((size_t)b*NN + n)*NN;
    float v[4];
    float mx = -1e30f;
    #pragma unroll
    for (int q = 0; q < 4; q++) { v[q] = Sr[t + q*256]; mx = fmaxf(mx, v[q]); }
    red[t] = mx; __syncthreads();
    for (int o = 128; o > 0; o >>= 1) { if (t < o) red[t] = fmaxf(red[t], red[t+o]); __syncthreads(); }
    mx = red[0]; __syncthreads();
    float s = 0.f;
    #pragma unroll
    for (int q = 0; q < 4; q++) { v[q] = expf(v[q] - mx); s += v[q]; }
    red[t] = s; __syncthreads();
    for (int o = 128; o > 0; o >>= 1) { if (t < o) red[t] += red[t+o]; __syncthreads(); }
    float inv = 1.f / red[0];
    float bta = fminf(fmaxf(beta[0], 0.f), 1.f);
    float din = g_dinv[n];
    float* Fr = Afus + ((size_t)b*NN + n)*NN;
    #pragma unroll
    for (int q = 0; q < 4; q++) {
        int j = t + q*256;
        float p = v[q] * inv;
        Sr[j] = p;
        Fr[j] = bta*p + (1.f - bta) * din * g_dinv[j] * Ast[(size_t)n*NN + j];
    }
}

// ---------------- diffusion hop: Xout[b,t] = A_fused[b] @ Xin[b,t] ---------
__global__ void k_diff(const float* __restrict__ Afus, int hop) {
    __shared__ __align__(16) float As[64*68];
    __shared__ __align__(16) float Xs[64*68];
    const float* Xin  = (hop == 0) ? g_Hp : g_X1;
    float*       Xout = (hop == 0) ? g_X1 : g_X2;
    int tid = threadIdx.x, tx = tid & 15, ty = tid >> 4;
    int i0 = blockIdx.x * 64;
    int bt = blockIdx.y;
    int b = bt / NT;
    const float* A = Afus + (size_t)b*NN*NN;
    const float* X = Xin + (size_t)bt*NN*64;
    float acc[4][4] = {};
    for (int kt = 0; kt < 16; kt++) {
        for (int l = tid; l < 4096; l += 256) {
            int r = l >> 6, c = l & 63;
            As[r*68 + c] = A[(size_t)(i0 + r)*NN + kt*64 + c];
            Xs[r*68 + c] = X[(size_t)(kt*64 + r)*64 + c];
        }
        __syncthreads();
        gemm_tile(As, Xs, acc, ty, tx);
        __syncthreads();
    }
    float* C = Xout + (size_t)bt*NN*64;
    #pragma unroll
    for (int i = 0; i < 4; i++)
        #pragma unroll
        for (int j = 0; j < 4; j++)
            C[(size_t)(i0 + ty*4+i)*64 + tx*4+j] = acc[i][j];
}

// ---------------- projection (K=192 over 3 sources) + final LN -------------
__global__ void k_proj(const float* __restrict__ pW, const float* __restrict__ pb,
                       const float* __restrict__ lng, const float* __restrict__ lnb,
                       float* __restrict__ Out) {
    __shared__ __align__(16) float As[64*68];
    __shared__ __align__(16) float Bs[64*68];
    __shared__ float rmean[64], rinv[64];
    int tid = threadIdx.x, tx = tid & 15, ty = tid >> 4;
    int row0 = blockIdx.x * 64;
    float acc[4][4] = {};
    for (int kt = 0; kt < 3; kt++) {
        const float* S = (kt == 0) ? g_Hp : (kt == 1) ? g_X1 : g_X2;
        for (int l = tid; l < 4096; l += 256) {
            int r = l >> 6, kk = l & 63;
            As[r*68 + kk] = S[(size_t)(row0 + r)*64 + kk];
            Bs[kk*68 + r] = pW[(size_t)r*192 + kt*64 + kk];   // r == o here
        }
        __syncthreads();
        gemm_tile(As, Bs, acc, ty, tx);
        __syncthreads();
    }
    #pragma unroll
    for (int i = 0; i < 4; i++)
        #pragma unroll
        for (int j = 0; j < 4; j++) {
            int c = tx*4+j;
            As[(ty*4+i)*68 + c] = acc[i][j] + pb[c];
        }
    __syncthreads();
    if (tid < 64) {
        float s = 0.f;
        for (int c = 0; c < 64; c++) s += As[tid*68 + c];
        float mu = s * (1.f/64.f);
        float v = 0.f;
        for (int c = 0; c < 64; c++) { float d_ = As[tid*68 + c] - mu; v += d_*d_; }
        rmean[tid] = mu;
        rinv[tid]  = rsqrtf(v*(1.f/64.f) + 1e-5f);
    }
    __syncthreads();
    #pragma unroll
    for (int i = 0; i < 4; i++)
        #pragma unroll
        for (int j = 0; j < 4; j++) {
            int r = ty*4+i, c = tx*4+j;
            float v = (As[r*68 + c] - rmean[r]) * rinv[r] * lng[c] + lnb[c];
            Out[(size_t)(row0 + r)*64 + c] = v;
        }
}

// ---------------- launch ----------------------------------------------------
extern "C" void kernel_launch(void* const* d_in, const int* in_sizes, int n_in,
                              void* d_out, int out_size) {
    const float* H    = (const float*)d_in[0];
    const float* Ast  = (const float*)d_in[1];
    const float* WQ   = (const float*)d_in[2];
    const float* WK   = (const float*)d_in[3];
    const float* WV   = (const float*)d_in[4];
    const float* PHI  = (const float*)d_in[5];
    const float* outW = (const float*)d_in[6];
    const float* outb = (const float*)d_in[7];
    const float* smag = (const float*)d_in[8];
    const float* smab = (const float*)d_in[9];
    const float* beta = (const float*)d_in[10];
    const float* pW   = (const float*)d_in[11];
    const float* pb   = (const float*)d_in[12];
    const float* agg  = (const float*)d_in[13];
    const float* agb  = (const float*)d_in[14];

    float* out  = (float*)d_out;
    float* Hsp  = out;                                    // [B,T,N,D]
    float* Adyn = out + (size_t)ROWS_TOT*64;              // [B,N,N]
    float* Afus = Adyn + (size_t)NB*NN*NN;                // [B,N,N]

    cudaFuncSetAttribute(k_attn, cudaFuncAttributeMaxDynamicSharedMemorySize, SMEM_ATTN);

    k_pre<<<1, 256>>>(PHI, WK, WV);
    k_deg<<<NN, 256>>>(Ast);
    k_zero<<<(NB*NN*ND + 255)/256, 256>>>();
    k_attn<<<ROWS_TOT/64, 256, SMEM_ATTN>>>(H, WQ, outW, outb, smag, smab);
    dim3 gS(16, 16, NB);
    k_mvS<<<gS, 256>>>(Adyn);
    dim3 gF(NN, NB);
    k_softfuse<<<gF, 256>>>(Adyn, Afus, Ast, beta);
    dim3 gD(16, NB*NT);
    k_diff<<<gD, 256>>>(Afus, 0);
    k_diff<<<gD, 256>>>(Afus, 1);
    k_proj<<<ROWS_TOT/64, 256>>>(pW, pb, agg, agb, Hsp);
}

// round 5
// speedup vs baseline: 1.1505x; 1.1505x over previous
#include <cuda_runtime.h>
#include <cuda_bf16.h>
#include <mma.h>
#include <math.h>
#include <cstdint>

using namespace nvcuda;

#define NB 8
#define NT 12
#define NN 1024
#define ND 64
#define NE 64
#define NM 16
#define ROWS_TOT (NB*NT*NN)      // 98304

// ---------------- scratch (device globals; allocation-free rule) ----------
__device__ float g_phiK[NM*NE];          // [m][e]
__device__ float g_V[NM*ND];             // [m][d]
__device__ float g_KtV[NE*ND];           // [e][d]
__device__ float g_dinv[NN];
__device__ float g_mv[NB*NN*ND];         // mean over t of mem_val
__device__ float g_Hp[ROWS_TOT*ND];      // H_prime
__device__ float g_X1[ROWS_TOT*ND];
__device__ float g_X2[ROWS_TOT*ND];

// ---------------- small precompute ----------------------------------------
__global__ void k_pre(const float* __restrict__ PHI, const float* __restrict__ WK,
                      const float* __restrict__ WV) {
    __shared__ float sK[NM*NE];
    __shared__ float sV[NM*ND];
    int t = threadIdx.x;
    for (int i = t; i < NM*NE; i += 256) {
        int m = i >> 6, de = i & 63;
        float s = 0.f, sv = 0.f;
        for (int j = 0; j < NE; j++) {
            float p = PHI[m*NE + j];
            s  += p * WK[de*NE + j];
            sv += p * WV[de*NE + j];
        }
        float pk = (s > 0.f) ? s + 1.f : expf(s);   // elu+1
        sK[i] = pk; g_phiK[i] = pk;
        sV[i] = sv; g_V[i] = sv;
    }
    __syncthreads();
    for (int i = t; i < NE*ND; i += 256) {
        int e = i >> 6, d = i & 63;
        float s = 0.f;
        #pragma unroll
        for (int m = 0; m < NM; m++) s += sK[m*NE + e] * sV[m*ND + d];
        g_KtV[i] = s;
    }
}

__global__ void k_deg(const float* __restrict__ A) {
    __shared__ float red[256];
    int n = blockIdx.x, t = threadIdx.x;
    float s = 0.f;
    for (int j = t; j < NN; j += 256) s += A[(size_t)n*NN + j];
    red[t] = s; __syncthreads();
    for (int o = 128; o > 0; o >>= 1) { if (t < o) red[t] += red[t+o]; __syncthreads(); }
    if (t == 0) g_dinv[n] = rsqrtf(red[0] + 1e-12f);
}

__global__ void k_zero() {
    int i = blockIdx.x*256 + threadIdx.x;
    if (i < NB*NN*ND) g_mv[i] = 0.f;
}

// ---------------- shared-tile fp32 GEMM microkernel ------------------------
__device__ __forceinline__ void gemm_tile(const float* __restrict__ As,
                                          const float* __restrict__ Bs,
                                          float acc[4][4], int ty, int tx) {
    #pragma unroll 4
    for (int kk = 0; kk < 64; kk++) {
        float a0 = As[(ty*4+0)*68 + kk];
        float a1 = As[(ty*4+1)*68 + kk];
        float a2 = As[(ty*4+2)*68 + kk];
        float a3 = As[(ty*4+3)*68 + kk];
        float4 b4 = *(const float4*)(Bs + kk*68 + tx*4);
        acc[0][0] += a0*b4.x; acc[0][1] += a0*b4.y; acc[0][2] += a0*b4.z; acc[0][3] += a0*b4.w;
        acc[1][0] += a1*b4.x; acc[1][1] += a1*b4.y; acc[1][2] += a1*b4.z; acc[1][3] += a1*b4.w;
        acc[2][0] += a2*b4.x; acc[2][1] += a2*b4.y; acc[2][2] += a2*b4.z; acc[2][3] += a2*b4.w;
        acc[3][0] += a3*b4.x; acc[3][1] += a3*b4.y; acc[3][2] += a3*b4.z; acc[3][3] += a3*b4.w;
    }
}

// ---------------- fused attention + out proj + LN (64-row tiles) -----------
#define SMEM_ATTN ((3*64*68 + 64*20 + 1024 + 1024 + 128) * 4)

__global__ void k_attn(const float* __restrict__ H, const float* __restrict__ WQ,
                       const float* __restrict__ outW, const float* __restrict__ outb,
                       const float* __restrict__ lng, const float* __restrict__ lnb) {
    extern __shared__ __align__(16) float sm[];
    float* Hs    = sm;
    float* Ps    = Hs + 64*68;
    float* Bs    = Ps + 64*68;
    float* QKs   = Bs + 64*68;
    float* phiKs = QKs + 64*20;
    float* Vs    = phiKs + 1024;
    float* rmean = Vs + 1024;
    float* rinv  = rmean + 64;

    int tid = threadIdx.x;
    int tx = tid & 15, ty = tid >> 4;
    int row0 = blockIdx.x * 64;
    const float* Hb = H + (size_t)row0 * 64;

    for (int l = tid; l < 4096; l += 256) {
        int r = l >> 6, c = l & 63;
        Hs[r*68 + c] = Hb[l];
        Bs[c*68 + r] = WQ[l];
    }
    for (int l = tid; l < 1024; l += 256) { phiKs[l] = g_phiK[l]; Vs[l] = g_V[l]; }
    __syncthreads();

    {
        float acc[4][4] = {};
        gemm_tile(Hs, Bs, acc, ty, tx);
        #pragma unroll
        for (int i = 0; i < 4; i++)
            #pragma unroll
            for (int j = 0; j < 4; j++) {
                float q = acc[i][j];
                Ps[(ty*4+i)*68 + tx*4+j] = (q > 0.f) ? q + 1.f : expf(q);
            }
    }
    __syncthreads();

    {
        int r = tid >> 2, mg = tid & 3;
        #pragma unroll
        for (int mm = 0; mm < 4; mm++) {
            int m = mg*4 + mm;
            float s = 0.f;
            for (int e = 0; e < 64; e++) s += Ps[r*68 + e] * phiKs[m*64 + e];
            QKs[r*20 + m] = s * 0.125f;
        }
    }
    __syncthreads();

    if (tid < 64) {
        float mx = -1e30f;
        #pragma unroll
        for (int m = 0; m < 16; m++) mx = fmaxf(mx, QKs[tid*20 + m]);
        float s = 0.f;
        #pragma unroll
        for (int m = 0; m < 16; m++) { float e_ = expf(QKs[tid*20 + m] - mx); QKs[tid*20 + m] = e_; s += e_; }
        float inv = 1.f / s;
        #pragma unroll
        for (int m = 0; m < 16; m++) QKs[tid*20 + m] *= inv;
    }
    for (int l = tid; l < 4096; l += 256)
        Bs[(l >> 6)*68 + (l & 63)] = g_KtV[l];
    __syncthreads();

    {
        int r = tid >> 2, dq = tid & 3;
        int grow = row0 + r;
        int b_ = grow / (NT*NN);
        int n_ = grow & (NN - 1);
        float am[16];
        #pragma unroll
        for (int m = 0; m < 16; m++) am[m] = QKs[r*20 + m];
        float* mvp = g_mv + ((size_t)(b_*NN + n_))*64 + dq*16;
        #pragma unroll
        for (int dd = 0; dd < 16; dd++) {
            float s = 0.f;
            #pragma unroll
            for (int m = 0; m < 16; m++) s += am[m] * Vs[m*64 + dq*16 + dd];
            atomicAdd(mvp + dd, s * (1.f/NT));
        }
    }

    {
        float acc[4][4] = {};
        gemm_tile(Ps, Bs, acc, ty, tx);
        #pragma unroll
        for (int i = 0; i < 4; i++)
            #pragma unroll
            for (int j = 0; j < 4; j++) {
                int pos = (ty*4+i)*68 + tx*4+j;
                Hs[pos] += acc[i][j];
            }
    }
    __syncthreads();
    for (int l = tid; l < 4096; l += 256) {
        int o = l >> 6, kk = l & 63;
        Bs[kk*68 + o] = outW[l];
    }
    __syncthreads();

    {
        float acc[4][4] = {};
        gemm_tile(Hs, Bs, acc, ty, tx);
        #pragma unroll
        for (int i = 0; i < 4; i++)
            #pragma unroll
            for (int j = 0; j < 4; j++) {
                int c = tx*4+j;
                Ps[(ty*4+i)*68 + c] = acc[i][j] + outb[c];
            }
    }
    __syncthreads();

    if (tid < 64) {
        float s = 0.f;
        for (int c = 0; c < 64; c++) s += Ps[tid*68 + c];
        float mu = s * (1.f/64.f);
        float v = 0.f;
        for (int c = 0; c < 64; c++) { float d_ = Ps[tid*68 + c] - mu; v += d_*d_; }
        rmean[tid] = mu;
        rinv[tid]  = rsqrtf(v*(1.f/64.f) + 1e-5f);
    }
    __syncthreads();
    #pragma unroll
    for (int i = 0; i < 4; i++)
        #pragma unroll
        for (int j = 0; j < 4; j++) {
            int r = ty*4+i, c = tx*4+j;
            float v = (Ps[r*68 + c] - rmean[r]) * rinv[r] * lng[c] + lnb[c];
            g_Hp[(size_t)(row0 + r)*64 + c] = v;
        }
}

// ---------------- A_dynamic logits: S = mv . mv^T / 8 ----------------------
__global__ void k_mvS(float* __restrict__ Sout) {
    __shared__ __align__(16) float Ai[64*68];
    __shared__ __align__(16) float Bt[64*68];
    int tid = threadIdx.x, tx = tid & 15, ty = tid >> 4;
    int i0 = blockIdx.x*64, j0 = blockIdx.y*64, b = blockIdx.z;
    const float* mvb = g_mv + (size_t)b*NN*64;
    for (int l = tid; l < 4096; l += 256) {
        int r = l >> 6, d = l & 63;
        Ai[r*68 + d] = mvb[(size_t)(i0 + r)*64 + d];
        Bt[d*68 + r] = mvb[(size_t)(j0 + r)*64 + d];
    }
    __syncthreads();
    float acc[4][4] = {};
    gemm_tile(Ai, Bt, acc, ty, tx);
    float* Sp = Sout + (size_t)b*NN*NN;
    #pragma unroll
    for (int i = 0; i < 4; i++)
        #pragma unroll
        for (int j = 0; j < 4; j++)
            Sp[(size_t)(i0 + ty*4+i)*NN + j0 + tx*4+j] = acc[i][j] * 0.125f;
}

// ---------------- in-place softmax + fuse ---------------------------------
__global__ void k_softfuse(float* __restrict__ Adyn, float* __restrict__ Afus,
                           const float* __restrict__ Ast, const float* __restrict__ beta) {
    __shared__ float red[256];
    int n = blockIdx.x, b = blockIdx.y, t = threadIdx.x;
    float* Sr = Adyn + ((size_t)b*NN + n)*NN;
    float v[4];
    float mx = -1e30f;
    #pragma unroll
    for (int q = 0; q < 4; q++) { v[q] = Sr[t + q*256]; mx = fmaxf(mx, v[q]); }
    red[t] = mx; __syncthreads();
    for (int o = 128; o > 0; o >>= 1) { if (t < o) red[t] = fmaxf(red[t], red[t+o]); __syncthreads(); }
    mx = red[0]; __syncthreads();
    float s = 0.f;
    #pragma unroll
    for (int q = 0; q < 4; q++) { v[q] = expf(v[q] - mx); s += v[q]; }
    red[t] = s; __syncthreads();
    for (int o = 128; o > 0; o >>= 1) { if (t < o) red[t] += red[t+o]; __syncthreads(); }
    float inv = 1.f / red[0];
    float bta = fminf(fmaxf(beta[0], 0.f), 1.f);
    float din = g_dinv[n];
    float* Fr = Afus + ((size_t)b*NN + n)*NN;
    #pragma unroll
    for (int q = 0; q < 4; q++) {
        int j = t + q*256;
        float p = v[q] * inv;
        Sr[j] = p;
        Fr[j] = bta*p + (1.f - bta) * din * g_dinv[j] * Ast[(size_t)n*NN + j];
    }
}

// ===== diffusion hop via WMMA bf16 (3-product split => ~1e-5 accuracy) =====
// Per CTA: D[128,64] = A_tile[128,1024] @ X[1024,64]; K chunks of 64.
// IMPORTANT: scratch globals are selected in DEVICE code via `hop` — passing
// __device__ array addresses from host code silently hands the kernel the
// host shadow symbol (ATS-reachable on GB300 => reads zeros, no fault).
#define A_LD 80
#define B_LD 80
#define DIFF_SMEM ((2*128*A_LD + 2*64*B_LD) * 2)

__device__ __forceinline__ void bf16_split(float a, __nv_bfloat16& h, __nv_bfloat16& l) {
    h = __float2bfloat16(a);
    l = __float2bfloat16(a - __bfloat162float(h));
}

__global__ void __launch_bounds__(256, 1)
k_diff_wmma(const float* __restrict__ Afus, int hop) {
    extern __shared__ __align__(16) __nv_bfloat16 smb[];
    __nv_bfloat16* Ah = smb;
    __nv_bfloat16* Al = Ah + 128*A_LD;
    __nv_bfloat16* Bh = Al + 128*A_LD;
    __nv_bfloat16* Bl = Bh + 64*B_LD;

    const float* Xin  = (hop == 0) ? g_Hp : g_X1;
    float*       Xout = (hop == 0) ? g_X1 : g_X2;

    int tid = threadIdx.x;
    int wid = tid >> 5;

    int i0 = blockIdx.x * 128;
    int bt = blockIdx.y;
    int b  = bt / NT;
    const float* A = Afus + (size_t)b*NN*NN + (size_t)i0*NN;
    const float* X = Xin + (size_t)bt*NN*64;

    wmma::fragment<wmma::accumulator, 16, 16, 16, float> facc[4];
    #pragma unroll
    for (int nt = 0; nt < 4; nt++) wmma::fill_fragment(facc[nt], 0.0f);

    for (int kt = 0; kt < 16; kt++) {
        // A tile 128x64 fp32 -> split bf16 hi/lo
        #pragma unroll
        for (int j = 0; j < 8; j++) {
            int idx = tid + 256*j;            // float4 index over 2048
            int r = idx >> 4, c4 = idx & 15;
            float4 v = *(const float4*)(A + (size_t)r*NN + kt*64 + c4*4);
            __nv_bfloat16 h0,l0,h1,l1,h2,l2,h3,l3;
            bf16_split(v.x, h0, l0); bf16_split(v.y, h1, l1);
            bf16_split(v.z, h2, l2); bf16_split(v.w, h3, l3);
            int base = r*A_LD + c4*4;
            *(__nv_bfloat162*)(Ah + base)     = __nv_bfloat162{h0, h1};
            *(__nv_bfloat162*)(Ah + base + 2) = __nv_bfloat162{h2, h3};
            *(__nv_bfloat162*)(Al + base)     = __nv_bfloat162{l0, l1};
            *(__nv_bfloat162*)(Al + base + 2) = __nv_bfloat162{l2, l3};
        }
        // X tile 64x64 fp32 -> split bf16 hi/lo
        #pragma unroll
        for (int j = 0; j < 4; j++) {
            int idx = tid + 256*j;            // float4 index over 1024
            int k = idx >> 4, n4 = idx & 15;
            float4 v = *(const float4*)(X + (size_t)(kt*64 + k)*64 + n4*4);
            __nv_bfloat16 h0,l0,h1,l1,h2,l2,h3,l3;
            bf16_split(v.x, h0, l0); bf16_split(v.y, h1, l1);
            bf16_split(v.z, h2, l2); bf16_split(v.w, h3, l3);
            int base = k*B_LD + n4*4;
            *(__nv_bfloat162*)(Bh + base)     = __nv_bfloat162{h0, h1};
            *(__nv_bfloat162*)(Bh + base + 2) = __nv_bfloat162{h2, h3};
            *(__nv_bfloat162*)(Bl + base)     = __nv_bfloat162{l0, l1};
            *(__nv_bfloat162*)(Bl + base + 2) = __nv_bfloat162{l2, l3};
        }
        __syncthreads();

        #pragma unroll
        for (int ks = 0; ks < 4; ks++) {
            wmma::fragment<wmma::matrix_a, 16, 16, 16, __nv_bfloat16, wmma::row_major> fah, fal;
            wmma::load_matrix_sync(fah, Ah + (wid*16)*A_LD + ks*16, A_LD);
            wmma::load_matrix_sync(fal, Al + (wid*16)*A_LD + ks*16, A_LD);
            #pragma unroll
            for (int nt = 0; nt < 4; nt++) {
                wmma::fragment<wmma::matrix_b, 16, 16, 16, __nv_bfloat16, wmma::row_major> fbh, fbl;
                wmma::load_matrix_sync(fbh, Bh + (ks*16)*B_LD + nt*16, B_LD);
                wmma::load_matrix_sync(fbl, Bl + (ks*16)*B_LD + nt*16, B_LD);
                wmma::mma_sync(facc[nt], fah, fbh, facc[nt]);
                wmma::mma_sync(facc[nt], fah, fbl, facc[nt]);
                wmma::mma_sync(facc[nt], fal, fbh, facc[nt]);
            }
        }
        __syncthreads();
    }

    // epilogue: warp wid owns rows [i0 + wid*16, +16)
    float* C = Xout + (size_t)bt*NN*64 + (size_t)(i0 + wid*16)*64;
    #pragma unroll
    for (int nt = 0; nt < 4; nt++)
        wmma::store_matrix_sync(C + nt*16, facc[nt], 64, wmma::mem_row_major);
}

// ---------------- projection (K=192 over 3 sources) + final LN -------------
__global__ void k_proj(const float* __restrict__ pW, const float* __restrict__ pb,
                       const float* __restrict__ lng, const float* __restrict__ lnb,
                       float* __restrict__ Out) {
    __shared__ __align__(16) float As[64*68];
    __shared__ __align__(16) float Bs[64*68];
    __shared__ float rmean[64], rinv[64];
    int tid = threadIdx.x, tx = tid & 15, ty = tid >> 4;
    int row0 = blockIdx.x * 64;
    float acc[4][4] = {};
    for (int kt = 0; kt < 3; kt++) {
        const float* S = (kt == 0) ? g_Hp : (kt == 1) ? g_X1 : g_X2;
        for (int l = tid; l < 4096; l += 256) {
            int r = l >> 6, kk = l & 63;
            As[r*68 + kk] = S[(size_t)(row0 + r)*64 + kk];
            Bs[kk*68 + r] = pW[(size_t)r*192 + kt*64 + kk];
        }
        __syncthreads();
        gemm_tile(As, Bs, acc, ty, tx);
        __syncthreads();
    }
    #pragma unroll
    for (int i = 0; i < 4; i++)
        #pragma unroll
        for (int j = 0; j < 4; j++) {
            int c = tx*4+j;
            As[(ty*4+i)*68 + c] = acc[i][j] + pb[c];
        }
    __syncthreads();
    if (tid < 64) {
        float s = 0.f;
        for (int c = 0; c < 64; c++) s += As[tid*68 + c];
        float mu = s * (1.f/64.f);
        float v = 0.f;
        for (int c = 0; c < 64; c++) { float d_ = As[tid*68 + c] - mu; v += d_*d_; }
        rmean[tid] = mu;
        rinv[tid]  = rsqrtf(v*(1.f/64.f) + 1e-5f);
    }
    __syncthreads();
    #pragma unroll
    for (int i = 0; i < 4; i++)
        #pragma unroll
        for (int j = 0; j < 4; j++) {
            int r = ty*4+i, c = tx*4+j;
            float v = (As[r*68 + c] - rmean[r]) * rinv[r] * lng[c] + lnb[c];
            Out[(size_t)(row0 + r)*64 + c] = v;
        }
}

// ---------------- launch ----------------------------------------------------
extern "C" void kernel_launch(void* const* d_in, const int* in_sizes, int n_in,
                              void* d_out, int out_size) {
    const float* H    = (const float*)d_in[0];
    const float* Ast  = (const float*)d_in[1];
    const float* WQ   = (const float*)d_in[2];
    const float* WK   = (const float*)d_in[3];
    const float* WV   = (const float*)d_in[4];
    const float* PHI  = (const float*)d_in[5];
    const float* outW = (const float*)d_in[6];
    const float* outb = (const float*)d_in[7];
    const float* smag = (const float*)d_in[8];
    const float* smab = (const float*)d_in[9];
    const float* beta = (const float*)d_in[10];
    const float* pW   = (const float*)d_in[11];
    const float* pb   = (const float*)d_in[12];
    const float* agg  = (const float*)d_in[13];
    const float* agb  = (const float*)d_in[14];

    float* out  = (float*)d_out;
    float* Hsp  = out;                                    // [B,T,N,D]
    float* Adyn = out + (size_t)ROWS_TOT*64;              // [B,N,N]
    float* Afus = Adyn + (size_t)NB*NN*NN;                // [B,N,N]

    cudaFuncSetAttribute(k_attn, cudaFuncAttributeMaxDynamicSharedMemorySize, SMEM_ATTN);
    cudaFuncSetAttribute(k_diff_wmma, cudaFuncAttributeMaxDynamicSharedMemorySize, DIFF_SMEM);

    k_pre<<<1, 256>>>(PHI, WK, WV);
    k_deg<<<NN, 256>>>(Ast);
    k_zero<<<(NB*NN*ND + 255)/256, 256>>>();
    k_attn<<<ROWS_TOT/64, 256, SMEM_ATTN>>>(H, WQ, outW, outb, smag, smab);
    dim3 gS(16, 16, NB);
    k_mvS<<<gS, 256>>>(Adyn);
    dim3 gF(NN, NB);
    k_softfuse<<<gF, 256>>>(Adyn, Afus, Ast, beta);
    dim3 gD(8, NB*NT);
    k_diff_wmma<<<gD, 256, DIFF_SMEM>>>(Afus, 0);
    k_diff_wmma<<<gD, 256, DIFF_SMEM>>>(Afus, 1);
    k_proj<<<ROWS_TOT/64, 256>>>(pW, pb, agg, agb, Hsp);
}

// round 10
// speedup vs baseline: 1.4462x; 1.2570x over previous
#include <cuda_runtime.h>
#include <cuda_bf16.h>
#include <mma.h>
#include <math.h>
#include <cstdint>

using namespace nvcuda;

#define NB 8
#define NT 12
#define NN 1024
#define ND 64
#define NE 64
#define NM 16
#define ROWS_TOT (NB*NT*NN)      // 98304

// ---------------- scratch (device globals; allocation-free rule) ----------
__device__ float g_phiK[NM*NE];          // [m][e]
__device__ float g_V[NM*ND];             // [m][d]
__device__ float g_KtV[NE*ND];           // [e][d]
__device__ float g_dinv[NN];
__device__ float g_mv[NB*NN*ND];         // mean over t of mem_val
// bf16 hi/lo split tensors (split once, consumed by wmma GEMMs)
__device__ __nv_bfloat16 g_Ah[(size_t)NB*NN*NN];   // A_fused hi
__device__ __nv_bfloat16 g_Al[(size_t)NB*NN*NN];   // A_fused lo
__device__ __nv_bfloat16 g_Xh[3][(size_t)ROWS_TOT*ND];  // {Hp, X1, X2} hi
__device__ __nv_bfloat16 g_Xl[3][(size_t)ROWS_TOT*ND];  // {Hp, X1, X2} lo
__device__ __nv_bfloat16 g_pWh[3*64*64];  // proj_W^T split, [kt][k][n]
__device__ __nv_bfloat16 g_pWl[3*64*64];

__device__ __forceinline__ void bf16_split(float a, __nv_bfloat16& h, __nv_bfloat16& l) {
    h = __float2bfloat16(a);
    l = __float2bfloat16(a - __bfloat162float(h));
}

// ---------------- small precompute ----------------------------------------
__global__ void k_pre(const float* __restrict__ PHI, const float* __restrict__ WK,
                      const float* __restrict__ WV, const float* __restrict__ pW) {
    __shared__ float sK[NM*NE];
    __shared__ float sV[NM*ND];
    int t = threadIdx.x;
    for (int i = t; i < NM*NE; i += 256) {
        int m = i >> 6, de = i & 63;
        float s = 0.f, sv = 0.f;
        for (int j = 0; j < NE; j++) {
            float p = PHI[m*NE + j];
            s  += p * WK[de*NE + j];
            sv += p * WV[de*NE + j];
        }
        float pk = (s > 0.f) ? s + 1.f : expf(s);   // elu+1
        sK[i] = pk; g_phiK[i] = pk;
        sV[i] = sv; g_V[i] = sv;
    }
    __syncthreads();
    for (int i = t; i < NE*ND; i += 256) {
        int e = i >> 6, d = i & 63;
        float s = 0.f;
        #pragma unroll
        for (int m = 0; m < NM; m++) s += sK[m*NE + e] * sV[m*ND + d];
        g_KtV[i] = s;
    }
    // proj_W^T bf16 split: g_pW[kt*4096 + k*64 + n] = pW[n*192 + kt*64 + k]
    for (int i = t; i < 3*64*64; i += 256) {
        int kt = i >> 12, k = (i >> 6) & 63, n = i & 63;
        float w = pW[(size_t)n*192 + kt*64 + k];
        __nv_bfloat16 h, l; bf16_split(w, h, l);
        g_pWh[i] = h; g_pWl[i] = l;
    }
}

__global__ void k_deg(const float* __restrict__ A) {
    __shared__ float red[256];
    int n = blockIdx.x, t = threadIdx.x;
    float s = 0.f;
    for (int j = t; j < NN; j += 256) s += A[(size_t)n*NN + j];
    red[t] = s; __syncthreads();
    for (int o = 128; o > 0; o >>= 1) { if (t < o) red[t] += red[t+o]; __syncthreads(); }
    if (t == 0) g_dinv[n] = rsqrtf(red[0] + 1e-12f);
}

__global__ void k_zero() {
    int i = blockIdx.x*256 + threadIdx.x;
    if (i < NB*NN*ND) g_mv[i] = 0.f;
}

// ---------------- shared-tile fp32 GEMM microkernel ------------------------
__device__ __forceinline__ void gemm_tile(const float* __restrict__ As,
                                          const float* __restrict__ Bs,
                                          float acc[4][4], int ty, int tx) {
    #pragma unroll 4
    for (int kk = 0; kk < 64; kk++) {
        float a0 = As[(ty*4+0)*68 + kk];
        float a1 = As[(ty*4+1)*68 + kk];
        float a2 = As[(ty*4+2)*68 + kk];
        float a3 = As[(ty*4+3)*68 + kk];
        float4 b4 = *(const float4*)(Bs + kk*68 + tx*4);
        acc[0][0] += a0*b4.x; acc[0][1] += a0*b4.y; acc[0][2] += a0*b4.z; acc[0][3] += a0*b4.w;
        acc[1][0] += a1*b4.x; acc[1][1] += a1*b4.y; acc[1][2] += a1*b4.z; acc[1][3] += a1*b4.w;
        acc[2][0] += a2*b4.x; acc[2][1] += a2*b4.y; acc[2][2] += a2*b4.z; acc[2][3] += a2*b4.w;
        acc[3][0] += a3*b4.x; acc[3][1] += a3*b4.y; acc[3][2] += a3*b4.z; acc[3][3] += a3*b4.w;
    }
}

// ---------------- fused attention + out proj + LN (64-row tiles) -----------
#define SMEM_ATTN ((3*64*68 + 64*20 + 1024 + 1024 + 128) * 4)

__global__ void k_attn(const float* __restrict__ H, const float* __restrict__ WQ,
                       const float* __restrict__ outW, const float* __restrict__ outb,
                       const float* __restrict__ lng, const float* __restrict__ lnb) {
    extern __shared__ __align__(16) float sm[];
    float* Hs    = sm;
    float* Ps    = Hs + 64*68;
    float* Bs    = Ps + 64*68;
    float* QKs   = Bs + 64*68;
    float* phiKs = QKs + 64*20;
    float* Vs    = phiKs + 1024;
    float* rmean = Vs + 1024;
    float* rinv  = rmean + 64;

    int tid = threadIdx.x;
    int tx = tid & 15, ty = tid >> 4;
    int row0 = blockIdx.x * 64;
    const float* Hb = H + (size_t)row0 * 64;

    for (int l = tid; l < 4096; l += 256) {
        int r = l >> 6, c = l & 63;
        Hs[r*68 + c] = Hb[l];
        Bs[c*68 + r] = WQ[l];
    }
    for (int l = tid; l < 1024; l += 256) { phiKs[l] = g_phiK[l]; Vs[l] = g_V[l]; }
    __syncthreads();

    {
        float acc[4][4] = {};
        gemm_tile(Hs, Bs, acc, ty, tx);
        #pragma unroll
        for (int i = 0; i < 4; i++)
            #pragma unroll
            for (int j = 0; j < 4; j++) {
                float q = acc[i][j];
                Ps[(ty*4+i)*68 + tx*4+j] = (q > 0.f) ? q + 1.f : expf(q);
            }
    }
    __syncthreads();

    {
        int r = tid >> 2, mg = tid & 3;
        #pragma unroll
        for (int mm = 0; mm < 4; mm++) {
            int m = mg*4 + mm;
            float s = 0.f;
            for (int e = 0; e < 64; e++) s += Ps[r*68 + e] * phiKs[m*64 + e];
            QKs[r*20 + m] = s * 0.125f;
        }
    }
    __syncthreads();

    if (tid < 64) {
        float mx = -1e30f;
        #pragma unroll
        for (int m = 0; m < 16; m++) mx = fmaxf(mx, QKs[tid*20 + m]);
        float s = 0.f;
        #pragma unroll
        for (int m = 0; m < 16; m++) { float e_ = expf(QKs[tid*20 + m] - mx); QKs[tid*20 + m] = e_; s += e_; }
        float inv = 1.f / s;
        #pragma unroll
        for (int m = 0; m < 16; m++) QKs[tid*20 + m] *= inv;
    }
    for (int l = tid; l < 4096; l += 256)
        Bs[(l >> 6)*68 + (l & 63)] = g_KtV[l];
    __syncthreads();

    {
        int r = tid >> 2, dq = tid & 3;
        int grow = row0 + r;
        int b_ = grow / (NT*NN);
        int n_ = grow & (NN - 1);
        float am[16];
        #pragma unroll
        for (int m = 0; m < 16; m++) am[m] = QKs[r*20 + m];
        float* mvp = g_mv + ((size_t)(b_*NN + n_))*64 + dq*16;
        #pragma unroll
        for (int dd = 0; dd < 16; dd++) {
            float s = 0.f;
            #pragma unroll
            for (int m = 0; m < 16; m++) s += am[m] * Vs[m*64 + dq*16 + dd];
            atomicAdd(mvp + dd, s * (1.f/NT));
        }
    }

    {
        float acc[4][4] = {};
        gemm_tile(Ps, Bs, acc, ty, tx);
        #pragma unroll
        for (int i = 0; i < 4; i++)
            #pragma unroll
            for (int j = 0; j < 4; j++) {
                int pos = (ty*4+i)*68 + tx*4+j;
                Hs[pos] += acc[i][j];
            }
    }
    __syncthreads();
    for (int l = tid; l < 4096; l += 256) {
        int o = l >> 6, kk = l & 63;
        Bs[kk*68 + o] = outW[l];
    }
    __syncthreads();

    {
        float acc[4][4] = {};
        gemm_tile(Hs, Bs, acc, ty, tx);
        #pragma unroll
        for (int i = 0; i < 4; i++)
            #pragma unroll
            for (int j = 0; j < 4; j++) {
                int c = tx*4+j;
                Ps[(ty*4+i)*68 + c] = acc[i][j] + outb[c];
            }
    }
    __syncthreads();

    if (tid < 64) {
        float s = 0.f;
        for (int c = 0; c < 64; c++) s += Ps[tid*68 + c];
        float mu = s * (1.f/64.f);
        float v = 0.f;
        for (int c = 0; c < 64; c++) { float d_ = Ps[tid*68 + c] - mu; v += d_*d_; }
        rmean[tid] = mu;
        rinv[tid]  = rsqrtf(v*(1.f/64.f) + 1e-5f);
    }
    __syncthreads();
    #pragma unroll
    for (int i = 0; i < 4; i++)
        #pragma unroll
        for (int j = 0; j < 4; j++) {
            int r = ty*4+i, c = tx*4+j;
            float v = (Ps[r*68 + c] - rmean[r]) * rinv[r] * lng[c] + lnb[c];
            __nv_bfloat16 h, l; bf16_split(v, h, l);
            size_t idx = (size_t)(row0 + r)*64 + c;
            g_Xh[0][idx] = h; g_Xl[0][idx] = l;
        }
}

// ---------------- A_dynamic logits: S = mv . mv^T / 8 ----------------------
__global__ void k_mvS(float* __restrict__ Sout) {
    __shared__ __align__(16) float Ai[64*68];
    __shared__ __align__(16) float Bt[64*68];
    int tid = threadIdx.x, tx = tid & 15, ty = tid >> 4;
    int i0 = blockIdx.x*64, j0 = blockIdx.y*64, b = blockIdx.z;
    const float* mvb = g_mv + (size_t)b*NN*64;
    for (int l = tid; l < 4096; l += 256) {
        int r = l >> 6, d = l & 63;
        Ai[r*68 + d] = mvb[(size_t)(i0 + r)*64 + d];
        Bt[d*68 + r] = mvb[(size_t)(j0 + r)*64 + d];
    }
    __syncthreads();
    float acc[4][4] = {};
    gemm_tile(Ai, Bt, acc, ty, tx);
    float* Sp = Sout + (size_t)b*NN*NN;
    #pragma unroll
    for (int i = 0; i < 4; i++)
        #pragma unroll
        for (int j = 0; j < 4; j++)
            Sp[(size_t)(i0 + ty*4+i)*NN + j0 + tx*4+j] = acc[i][j] * 0.125f;
}

// -------- in-place softmax + fuse + bf16-split emit of A_fused -------------
__global__ void k_softfuse(float* __restrict__ Adyn, float* __restrict__ Afus,
                           const float* __restrict__ Ast, const float* __restrict__ beta) {
    __shared__ float red[256];
    int n = blockIdx.x, b = blockIdx.y, t = threadIdx.x;
    float* Sr = Adyn + ((size_t)b*NN + n)*NN;
    float v[4];
    float mx = -1e30f;
    #pragma unroll
    for (int q = 0; q < 4; q++) { v[q] = Sr[t + q*256]; mx = fmaxf(mx, v[q]); }
    red[t] = mx; __syncthreads();
    for (int o = 128; o > 0; o >>= 1) { if (t < o) red[t] = fmaxf(red[t], red[t+o]); __syncthreads(); }
    mx = red[0]; __syncthreads();
    float s = 0.f;
    #pragma unroll
    for (int q = 0; q < 4; q++) { v[q] = expf(v[q] - mx); s += v[q]; }
    red[t] = s; __syncthreads();
    for (int o = 128; o > 0; o >>= 1) { if (t < o) red[t] += red[t+o]; __syncthreads(); }
    float inv = 1.f / red[0];
    float bta = fminf(fmaxf(beta[0], 0.f), 1.f);
    float din = g_dinv[n];
    float* Fr = Afus + ((size_t)b*NN + n)*NN;
    size_t arow = ((size_t)b*NN + n)*NN;
    #pragma unroll
    for (int q = 0; q < 4; q++) {
        int j = t + q*256;
        float p = v[q] * inv;
        Sr[j] = p;
        float f = bta*p + (1.f - bta) * din * g_dinv[j] * Ast[(size_t)n*NN + j];
        Fr[j] = f;
        __nv_bfloat16 h, l; bf16_split(f, h, l);
        g_Ah[arow + j] = h; g_Al[arow + j] = l;
    }
}

// ===== diffusion hop via WMMA bf16 (pure-bf16 loads, 3-product split) ======
// Per CTA: D[128,64] = A_tile[128,1024] @ X[1024,64]; K chunks of 64.
// smem bf16: Ah[128*72] Al[128*72] Bh[64*72] Bl[64*72] = 55296 B
// Epilogue stages fp32 into aliased smem, then splits+writes bf16 outputs.
#define A_LD 72
#define DIFF_SMEM ((2*128*A_LD + 2*64*A_LD) * 2)

__global__ void __launch_bounds__(256)
k_diff_wmma(int hop) {
    extern __shared__ __align__(16) __nv_bfloat16 smb[];
    __nv_bfloat16* Ahs = smb;
    __nv_bfloat16* Als = Ahs + 128*A_LD;
    __nv_bfloat16* Bhs = Als + 128*A_LD;
    __nv_bfloat16* Bls = Bhs + 64*A_LD;

    const __nv_bfloat16* Bh_g = g_Xh[hop];
    const __nv_bfloat16* Bl_g = g_Xl[hop];
    __nv_bfloat16* Oh_g = g_Xh[hop + 1];
    __nv_bfloat16* Ol_g = g_Xl[hop + 1];

    int tid = threadIdx.x;
    int wid = tid >> 5;

    int i0 = blockIdx.x * 128;
    int bt = blockIdx.y;
    int b  = bt / NT;
    const __nv_bfloat16* Ah_g = g_Ah + (size_t)b*NN*NN + (size_t)i0*NN;
    const __nv_bfloat16* Al_g = g_Al + (size_t)b*NN*NN + (size_t)i0*NN;
    const __nv_bfloat16* Xh_g = Bh_g + (size_t)bt*NN*64;
    const __nv_bfloat16* Xl_g = Bl_g + (size_t)bt*NN*64;

    wmma::fragment<wmma::accumulator, 16, 16, 16, float> facc[4];
    #pragma unroll
    for (int nt = 0; nt < 4; nt++) wmma::fill_fragment(facc[nt], 0.0f);

    for (int kt = 0; kt < 16; kt++) {
        // A chunk [128 x 64] bf16: 8 uint4 per row; 1024 uint4 per half
        #pragma unroll
        for (int j = 0; j < 4; j++) {
            int idx = tid + 256*j;
            int r = idx >> 3, c8 = idx & 7;
            size_t go = (size_t)r*NN + kt*64 + c8*8;
            ((uint4*)Ahs)[r*9 + c8] = *(const uint4*)(Ah_g + go);
            ((uint4*)Als)[r*9 + c8] = *(const uint4*)(Al_g + go);
        }
        // B chunk [64 x 64] bf16: 512 uint4 per half
        #pragma unroll
        for (int j = 0; j < 2; j++) {
            int idx = tid + 256*j;
            int k = idx >> 3, c8 = idx & 7;
            size_t go = (size_t)(kt*64 + k)*64 + c8*8;
            ((uint4*)Bhs)[k*9 + c8] = *(const uint4*)(Xh_g + go);
            ((uint4*)Bls)[k*9 + c8] = *(const uint4*)(Xl_g + go);
        }
        __syncthreads();

        #pragma unroll
        for (int ks = 0; ks < 4; ks++) {
            wmma::fragment<wmma::matrix_a, 16, 16, 16, __nv_bfloat16, wmma::row_major> fah, fal;
            wmma::load_matrix_sync(fah, Ahs + (wid*16)*A_LD + ks*16, A_LD);
            wmma::load_matrix_sync(fal, Als + (wid*16)*A_LD + ks*16, A_LD);
            #pragma unroll
            for (int nt = 0; nt < 4; nt++) {
                wmma::fragment<wmma::matrix_b, 16, 16, 16, __nv_bfloat16, wmma::row_major> fbh, fbl;
                wmma::load_matrix_sync(fbh, Bhs + (ks*16)*A_LD + nt*16, A_LD);
                wmma::load_matrix_sync(fbl, Bls + (ks*16)*A_LD + nt*16, A_LD);
                wmma::mma_sync(facc[nt], fah, fbh, facc[nt]);
                wmma::mma_sync(facc[nt], fah, fbl, facc[nt]);
                wmma::mma_sync(facc[nt], fal, fbh, facc[nt]);
            }
        }
        __syncthreads();
    }

    // epilogue: stage fp32 in aliased smem, then split + write bf16
    float* Cs = (float*)smb;        // 128*68 fp32 = 34816 B < 55296
    #pragma unroll
    for (int nt = 0; nt < 4; nt++)
        wmma::store_matrix_sync(Cs + (wid*16)*68 + nt*16, facc[nt], 68, wmma::mem_row_major);
    __syncthreads();
    #pragma unroll
    for (int j = 0; j < 32; j++) {
        int idx = tid + 256*j;      // 8192 elems
        int r = idx >> 6, c = idx & 63;
        float v = Cs[r*68 + c];
        __nv_bfloat16 h, l; bf16_split(v, h, l);
        size_t go = ((size_t)bt*NN + i0 + r)*64 + c;
        Oh_g[go] = h; Ol_g[go] = l;
    }
}

// ====== projection via WMMA (K=192 in 3 chunks from bf16 splits) + LN ======
__global__ void __launch_bounds__(256)
k_proj(const float* __restrict__ pb,
       const float* __restrict__ lng, const float* __restrict__ lnb,
       float* __restrict__ Out) {
    extern __shared__ __align__(16) __nv_bfloat16 smb[];
    __nv_bfloat16* Ahs = smb;
    __nv_bfloat16* Als = Ahs + 128*A_LD;
    __nv_bfloat16* Bhs = Als + 128*A_LD;
    __nv_bfloat16* Bls = Bhs + 64*A_LD;

    int tid = threadIdx.x;
    int wid = tid >> 5;
    int row0 = blockIdx.x * 128;

    wmma::fragment<wmma::accumulator, 16, 16, 16, float> facc[4];
    #pragma unroll
    for (int nt = 0; nt < 4; nt++) wmma::fill_fragment(facc[nt], 0.0f);

    #pragma unroll
    for (int kt = 0; kt < 3; kt++) {
        const __nv_bfloat16* Sh = g_Xh[kt];
        const __nv_bfloat16* Sl = g_Xl[kt];
        #pragma unroll
        for (int j = 0; j < 4; j++) {
            int idx = tid + 256*j;
            int r = idx >> 3, c8 = idx & 7;
            size_t go = (size_t)(row0 + r)*64 + c8*8;
            ((uint4*)Ahs)[r*9 + c8] = *(const uint4*)(Sh + go);
            ((uint4*)Als)[r*9 + c8] = *(const uint4*)(Sl + go);
        }
        #pragma unroll
        for (int j = 0; j < 2; j++) {
            int idx = tid + 256*j;
            int k = idx >> 3, c8 = idx & 7;
            size_t go = (size_t)kt*4096 + (size_t)k*64 + c8*8;
            ((uint4*)Bhs)[k*9 + c8] = *(const uint4*)(g_pWh + go);
            ((uint4*)Bls)[k*9 + c8] = *(const uint4*)(g_pWl + go);
        }
        __syncthreads();

        #pragma unroll
        for (int ks = 0; ks < 4; ks++) {
            wmma::fragment<wmma::matrix_a, 16, 16, 16, __nv_bfloat16, wmma::row_major> fah, fal;
            wmma::load_matrix_sync(fah, Ahs + (wid*16)*A_LD + ks*16, A_LD);
            wmma::load_matrix_sync(fal, Als + (wid*16)*A_LD + ks*16, A_LD);
            #pragma unroll
            for (int nt = 0; nt < 4; nt++) {
                wmma::fragment<wmma::matrix_b, 16, 16, 16, __nv_bfloat16, wmma::row_major> fbh, fbl;
                wmma::load_matrix_sync(fbh, Bhs + (ks*16)*A_LD + nt*16, A_LD);
                wmma::load_matrix_sync(fbl, Bls + (ks*16)*A_LD + nt*16, A_LD);
                wmma::mma_sync(facc[nt], fah, fbh, facc[nt]);
                wmma::mma_sync(facc[nt], fah, fbl, facc[nt]);
                wmma::mma_sync(facc[nt], fal, fbh, facc[nt]);
            }
        }
        __syncthreads();
    }

    // epilogue: bias + LN, write fp32 output
    float* Cs = (float*)smb;                    // 128*68 fp32
    float* rmean = Cs + 128*68;                 // 128
    float* rinv  = rmean + 128;                 // 128
    #pragma unroll
    for (int nt = 0; nt < 4; nt++)
        wmma::store_matrix_sync(Cs + (wid*16)*68 + nt*16, facc[nt], 68, wmma::mem_row_major);
    __syncthreads();
    if (tid < 128) {
        float s = 0.f;
        for (int c = 0; c < 64; c++) s += Cs[tid*68 + c] + pb[c];
        float mu = s * (1.f/64.f);
        float v = 0.f;
        for (int c = 0; c < 64; c++) { float d_ = Cs[tid*68 + c] + pb[c] - mu; v += d_*d_; }
        rmean[tid] = mu;
        rinv[tid]  = rsqrtf(v*(1.f/64.f) + 1e-5f);
    }
    __syncthreads();
    #pragma unroll
    for (int j = 0; j < 32; j++) {
        int idx = tid + 256*j;
        int r = idx >> 6, c = idx & 63;
        float v = (Cs[r*68 + c] + pb[c] - rmean[r]) * rinv[r] * lng[c] + lnb[c];
        Out[(size_t)(row0 + r)*64 + c] = v;
    }
}

// ---------------- launch ----------------------------------------------------
extern "C" void kernel_launch(void* const* d_in, const int* in_sizes, int n_in,
                              void* d_out, int out_size) {
    const float* H    = (const float*)d_in[0];
    const float* Ast  = (const float*)d_in[1];
    const float* WQ   = (const float*)d_in[2];
    const float* WK   = (const float*)d_in[3];
    const float* WV   = (const float*)d_in[4];
    const float* PHI  = (const float*)d_in[5];
    const float* outW = (const float*)d_in[6];
    const float* outb = (const float*)d_in[7];
    const float* smag = (const float*)d_in[8];
    const float* smab = (const float*)d_in[9];
    const float* beta = (const float*)d_in[10];
    const float* pW   = (const float*)d_in[11];
    const float* pb   = (const float*)d_in[12];
    const float* agg  = (const float*)d_in[13];
    const float* agb  = (const float*)d_in[14];

    float* out  = (float*)d_out;
    float* Hsp  = out;                                    // [B,T,N,D]
    float* Adyn = out + (size_t)ROWS_TOT*64;              // [B,N,N]
    float* Afus = Adyn + (size_t)NB*NN*NN;                // [B,N,N]

    cudaFuncSetAttribute(k_attn, cudaFuncAttributeMaxDynamicSharedMemorySize, SMEM_ATTN);
    cudaFuncSetAttribute(k_diff_wmma, cudaFuncAttributeMaxDynamicSharedMemorySize, DIFF_SMEM);
    cudaFuncSetAttribute(k_proj, cudaFuncAttributeMaxDynamicSharedMemorySize, DIFF_SMEM);

    k_pre<<<1, 256>>>(PHI, WK, WV, pW);
    k_deg<<<NN, 256>>>(Ast);
    k_zero<<<(NB*NN*ND + 255)/256, 256>>>();
    k_attn<<<ROWS_TOT/64, 256, SMEM_ATTN>>>(H, WQ, outW, outb, smag, smab);
    dim3 gS(16, 16, NB);
    k_mvS<<<gS, 256>>>(Adyn);
    dim3 gF(NN, NB);
    k_softfuse<<<gF, 256>>>(Adyn, Afus, Ast, beta);
    dim3 gD(8, NB*NT);
    k_diff_wmma<<<gD, 256, DIFF_SMEM>>>(0);
    k_diff_wmma<<<gD, 256, DIFF_SMEM>>>(1);
    k_proj<<<ROWS_TOT/128, 256, DIFF_SMEM>>>(pb, agg, agb, Hsp);
}

// round 13
// speedup vs baseline: 1.5770x; 1.0904x over previous
#include <cuda_runtime.h>
#include <cuda_bf16.h>
#include <mma.h>
#include <math.h>
#include <cstdint>

using namespace nvcuda;

#define NB 8
#define NT 12
#define NN 1024
#define ND 64
#define NE 64
#define NM 16
#define ROWS_TOT (NB*NT*NN)      // 98304

// ---------------- scratch (device globals; allocation-free rule) ----------
__device__ float g_phiK[NM*NE];          // [m][e]
__device__ float g_V[NM*ND];             // [m][d]
__device__ float g_dinv[NN];
__device__ float g_mv[NB*NN*ND];         // mean over t of mem_val
// bf16 hi/lo split tensors (split once, consumed by wmma GEMMs)
__device__ __nv_bfloat16 g_Ah[(size_t)NB*NN*NN];   // A_fused hi
__device__ __nv_bfloat16 g_Al[(size_t)NB*NN*NN];   // A_fused lo
__device__ __nv_bfloat16 g_Xh[3][(size_t)ROWS_TOT*ND];  // {Hp, X1, X2} hi
__device__ __nv_bfloat16 g_Xl[3][(size_t)ROWS_TOT*ND];  // {Hp, X1, X2} lo
__device__ __nv_bfloat16 g_pWh[3*64*64];  // proj_W^T split, [kt][k][n]
__device__ __nv_bfloat16 g_pWl[3*64*64];
__device__ __nv_bfloat16 g_WQh[64*64];    // WQ^T split [d][e]
__device__ __nv_bfloat16 g_WQl[64*64];
__device__ __nv_bfloat16 g_KtVh[64*64];   // KtV split [e][d]
__device__ __nv_bfloat16 g_KtVl[64*64];
__device__ __nv_bfloat16 g_oWh[64*64];    // outW^T split [d][o]
__device__ __nv_bfloat16 g_oWl[64*64];
__device__ __nv_bfloat16 g_mvh[NB*NN*ND]; // mv split
__device__ __nv_bfloat16 g_mvl[NB*NN*ND];

__device__ __forceinline__ void bf16_split(float a, __nv_bfloat16& h, __nv_bfloat16& l) {
    h = __float2bfloat16(a);
    l = __float2bfloat16(a - __bfloat162float(h));
}

// ---------------- small precompute ----------------------------------------
__global__ void k_pre(const float* __restrict__ PHI, const float* __restrict__ WK,
                      const float* __restrict__ WV, const float* __restrict__ WQ,
                      const float* __restrict__ oW, const float* __restrict__ pW) {
    __shared__ float sK[NM*NE];
    __shared__ float sV[NM*ND];
    int t = threadIdx.x;
    for (int i = t; i < NM*NE; i += 256) {
        int m = i >> 6, de = i & 63;
        float s = 0.f, sv = 0.f;
        for (int j = 0; j < NE; j++) {
            float p = PHI[m*NE + j];
            s  += p * WK[de*NE + j];
            sv += p * WV[de*NE + j];
        }
        float pk = (s > 0.f) ? s + 1.f : expf(s);   // elu+1
        sK[i] = pk; g_phiK[i] = pk;
        sV[i] = sv; g_V[i] = sv;
    }
    __syncthreads();
    for (int i = t; i < NE*ND; i += 256) {          // KtV split, [e][d]
        int e = i >> 6, d = i & 63;
        float s = 0.f;
        #pragma unroll
        for (int m = 0; m < NM; m++) s += sK[m*NE + e] * sV[m*ND + d];
        __nv_bfloat16 h, l; bf16_split(s, h, l);
        g_KtVh[i] = h; g_KtVl[i] = l;
    }
    for (int i = t; i < NE*ND; i += 256) {          // WQ^T split: [d][e]
        int d = i >> 6, e = i & 63;
        __nv_bfloat16 h, l; bf16_split(WQ[e*64 + d], h, l);
        g_WQh[i] = h; g_WQl[i] = l;
    }
    for (int i = t; i < ND*ND; i += 256) {          // outW^T split: [d][o]
        int d = i >> 6, o = i & 63;
        __nv_bfloat16 h, l; bf16_split(oW[o*64 + d], h, l);
        g_oWh[i] = h; g_oWl[i] = l;
    }
    for (int i = t; i < 3*64*64; i += 256) {        // proj_W^T split
        int kt = i >> 12, k = (i >> 6) & 63, n = i & 63;
        __nv_bfloat16 h, l; bf16_split(pW[(size_t)n*192 + kt*64 + k], h, l);
        g_pWh[i] = h; g_pWl[i] = l;
    }
}

__global__ void k_deg(const float* __restrict__ A) {
    __shared__ float red[256];
    int n = blockIdx.x, t = threadIdx.x;
    float s = 0.f;
    for (int j = t; j < NN; j += 256) s += A[(size_t)n*NN + j];
    red[t] = s; __syncthreads();
    for (int o = 128; o > 0; o >>= 1) { if (t < o) red[t] += red[t+o]; __syncthreads(); }
    if (t == 0) g_dinv[n] = rsqrtf(red[0] + 1e-12f);
}

__global__ void k_zero() {
    int i = blockIdx.x*256 + threadIdx.x;
    if (i < NB*NN*ND) g_mv[i] = 0.f;
}

__global__ void k_splitmv() {
    int idx = blockIdx.x*256 + threadIdx.x;  // float4 index over 131072
    float4 v = ((const float4*)g_mv)[idx];
    __nv_bfloat16 h0,l0,h1,l1,h2,l2,h3,l3;
    bf16_split(v.x,h0,l0); bf16_split(v.y,h1,l1);
    bf16_split(v.z,h2,l2); bf16_split(v.w,h3,l3);
    int base = idx*4;
    *(__nv_bfloat162*)(g_mvh+base)   = __nv_bfloat162{h0,h1};
    *(__nv_bfloat162*)(g_mvh+base+2) = __nv_bfloat162{h2,h3};
    *(__nv_bfloat162*)(g_mvl+base)   = __nv_bfloat162{l0,l1};
    *(__nv_bfloat162*)(g_mvl+base+2) = __nv_bfloat162{l2,l3};
}

// ====== fused attention via WMMA: 128-row tiles, 256 threads ===============
// smem: Ah/Al 128*72 bf16, Bh/Bl 64*72 bf16 | Qs 128*68 f32, QKs 128*20,
//       phiKs 1024, Vs 1024, rmean/rinv 128 each.  Total 109,568 B -> 2 CTA/SM
#define ATTN_SMEM ((2*128*72 + 2*64*72)*2 + (128*68 + 128*20 + 1024 + 1024 + 256)*4)

__global__ void __launch_bounds__(256)
k_attn(const float* __restrict__ H, const float* __restrict__ outb,
       const float* __restrict__ lng, const float* __restrict__ lnb) {
    extern __shared__ __align__(16) __nv_bfloat16 smb[];
    __nv_bfloat16* Ah = smb;
    __nv_bfloat16* Al = Ah + 128*72;
    __nv_bfloat16* Bh = Al + 128*72;
    __nv_bfloat16* Bl = Bh + 64*72;
    float* Qs    = (float*)(Bl + 64*72);
    float* QKs   = Qs + 128*68;
    float* phiKs = QKs + 128*20;
    float* Vs    = phiKs + 1024;
    float* rmean = Vs + 1024;
    float* rinv  = rmean + 128;

    int tid = threadIdx.x, wid = tid >> 5;
    int row0 = blockIdx.x * 128;
    const float* Hb = H + (size_t)row0 * 64;

    // load: H split -> Ah/Al ; WQ^T splits -> Bh/Bl ; phiK, V
    #pragma unroll
    for (int j = 0; j < 8; j++) {
        int idx = tid + 256*j;             // float4 over 2048
        int r = idx >> 4, c4 = idx & 15;
        float4 v = *(const float4*)(Hb + idx*4);
        __nv_bfloat16 h0,l0,h1,l1,h2,l2,h3,l3;
        bf16_split(v.x,h0,l0); bf16_split(v.y,h1,l1);
        bf16_split(v.z,h2,l2); bf16_split(v.w,h3,l3);
        int base = r*72 + c4*4;
        *(__nv_bfloat162*)(Ah+base)   = __nv_bfloat162{h0,h1};
        *(__nv_bfloat162*)(Ah+base+2) = __nv_bfloat162{h2,h3};
        *(__nv_bfloat162*)(Al+base)   = __nv_bfloat162{l0,l1};
        *(__nv_bfloat162*)(Al+base+2) = __nv_bfloat162{l2,l3};
    }
    #pragma unroll
    for (int j = 0; j < 2; j++) {
        int idx = tid + 256*j;             // uint4 over 512
        int k = idx >> 3, c8 = idx & 7;
        *(uint4*)(Bh + k*72 + c8*8) = *(const uint4*)(g_WQh + k*64 + c8*8);
        *(uint4*)(Bl + k*72 + c8*8) = *(const uint4*)(g_WQl + k*64 + c8*8);
    }
    for (int l = tid; l < 1024; l += 256) { phiKs[l] = g_phiK[l]; Vs[l] = g_V[l]; }
    __syncthreads();

    // GEMM1: Q = H*WQ^T ; elu+1 elementwise on fragments ; -> Qs (phiQ fp32)
    {
        wmma::fragment<wmma::accumulator,16,16,16,float> fc[4];
        #pragma unroll
        for (int nt = 0; nt < 4; nt++) wmma::fill_fragment(fc[nt], 0.f);
        #pragma unroll
        for (int ks = 0; ks < 4; ks++) {
            wmma::fragment<wmma::matrix_a,16,16,16,__nv_bfloat16,wmma::row_major> fah, fal;
            wmma::load_matrix_sync(fah, Ah + (wid*16)*72 + ks*16, 72);
            wmma::load_matrix_sync(fal, Al + (wid*16)*72 + ks*16, 72);
            #pragma unroll
            for (int nt = 0; nt < 4; nt++) {
                wmma::fragment<wmma::matrix_b,16,16,16,__nv_bfloat16,wmma::row_major> fbh, fbl;
                wmma::load_matrix_sync(fbh, Bh + (ks*16)*72 + nt*16, 72);
                wmma::load_matrix_sync(fbl, Bl + (ks*16)*72 + nt*16, 72);
                wmma::mma_sync(fc[nt], fah, fbh, fc[nt]);
                wmma::mma_sync(fc[nt], fah, fbl, fc[nt]);
                wmma::mma_sync(fc[nt], fal, fbh, fc[nt]);
            }
        }
        #pragma unroll
        for (int nt = 0; nt < 4; nt++) {
            #pragma unroll
            for (int i = 0; i < fc[nt].num_elements; i++) {
                float q = fc[nt].x[i];
                fc[nt].x[i] = (q > 0.f) ? q + 1.f : expf(q);
            }
            wmma::store_matrix_sync(Qs + (wid*16)*68 + nt*16, fc[nt], 68, wmma::mem_row_major);
        }
    }
    __syncthreads();

    // split phiQ -> Ah/Al ; Bh/Bl <- KtV splits ; QK from Qs
    #pragma unroll
    for (int j = 0; j < 32; j++) {
        int idx = tid + 256*j;
        int r = idx >> 6, c = idx & 63;
        __nv_bfloat16 h, l; bf16_split(Qs[r*68 + c], h, l);
        Ah[r*72 + c] = h; Al[r*72 + c] = l;
    }
    #pragma unroll
    for (int j = 0; j < 2; j++) {
        int idx = tid + 256*j;
        int k = idx >> 3, c8 = idx & 7;
        *(uint4*)(Bh + k*72 + c8*8) = *(const uint4*)(g_KtVh + k*64 + c8*8);
        *(uint4*)(Bl + k*72 + c8*8) = *(const uint4*)(g_KtVl + k*64 + c8*8);
    }
    {
        int r = tid >> 1, mg = tid & 1;
        float s[8] = {};
        for (int e = 0; e < 64; e++) {
            float q = Qs[r*68 + e];
            #pragma unroll
            for (int mm = 0; mm < 8; mm++)
                s[mm] += q * phiKs[(mg*8 + mm)*64 + e];
        }
        #pragma unroll
        for (int mm = 0; mm < 8; mm++) QKs[r*20 + mg*8 + mm] = s[mm] * 0.125f;
    }
    __syncthreads();

    // softmax over M=16 per row
    if (tid < 128) {
        float mx = -1e30f;
        #pragma unroll
        for (int m = 0; m < 16; m++) mx = fmaxf(mx, QKs[tid*20 + m]);
        float ss = 0.f;
        #pragma unroll
        for (int m = 0; m < 16; m++) { float e_ = expf(QKs[tid*20 + m] - mx); QKs[tid*20 + m] = e_; ss += e_; }
        float inv = 1.f / ss;
        #pragma unroll
        for (int m = 0; m < 16; m++) QKs[tid*20 + m] *= inv;
    }
    __syncthreads();

    // mem_val -> mv (mean over t via atomic)
    {
        int r = tid >> 1, dq = tid & 1;
        int grow = row0 + r;
        int b_ = grow / (NT*NN);
        int n_ = grow & (NN - 1);
        float am[16];
        #pragma unroll
        for (int m = 0; m < 16; m++) am[m] = QKs[r*20 + m];
        float* mvp = g_mv + ((size_t)(b_*NN + n_))*64 + dq*32;
        #pragma unroll
        for (int dd = 0; dd < 32; dd++) {
            float s = 0.f;
            #pragma unroll
            for (int m = 0; m < 16; m++) s += am[m] * Vs[m*64 + dq*32 + dd];
            atomicAdd(mvp + dd, s * (1.f/NT));
        }
    }

    // GEMM2: main_att = phiQ*KtV -> Qs
    {
        wmma::fragment<wmma::accumulator,16,16,16,float> fc[4];
        #pragma unroll
        for (int nt = 0; nt < 4; nt++) wmma::fill_fragment(fc[nt], 0.f);
        #pragma unroll
        for (int ks = 0; ks < 4; ks++) {
            wmma::fragment<wmma::matrix_a,16,16,16,__nv_bfloat16,wmma::row_major> fah, fal;
            wmma::load_matrix_sync(fah, Ah + (wid*16)*72 + ks*16, 72);
            wmma::load_matrix_sync(fal, Al + (wid*16)*72 + ks*16, 72);
            #pragma unroll
            for (int nt = 0; nt < 4; nt++) {
                wmma::fragment<wmma::matrix_b,16,16,16,__nv_bfloat16,wmma::row_major> fbh, fbl;
                wmma::load_matrix_sync(fbh, Bh + (ks*16)*72 + nt*16, 72);
                wmma::load_matrix_sync(fbl, Bl + (ks*16)*72 + nt*16, 72);
                wmma::mma_sync(fc[nt], fah, fbh, fc[nt]);
                wmma::mma_sync(fc[nt], fah, fbl, fc[nt]);
                wmma::mma_sync(fc[nt], fal, fbh, fc[nt]);
            }
        }
        #pragma unroll
        for (int nt = 0; nt < 4; nt++)
            wmma::store_matrix_sync(Qs + (wid*16)*68 + nt*16, fc[nt], 68, wmma::mem_row_major);
    }
    __syncthreads();

    // Hp = main + H (H reloaded from gmem) ; split -> Ah/Al ; Bh/Bl <- outW^T
    #pragma unroll
    for (int j = 0; j < 32; j++) {
        int idx = tid + 256*j;
        int r = idx >> 6, c = idx & 63;
        float v = Qs[r*68 + c] + Hb[idx];
        __nv_bfloat16 h, l; bf16_split(v, h, l);
        Ah[r*72 + c] = h; Al[r*72 + c] = l;
    }
    #pragma unroll
    for (int j = 0; j < 2; j++) {
        int idx = tid + 256*j;
        int k = idx >> 3, c8 = idx & 7;
        *(uint4*)(Bh + k*72 + c8*8) = *(const uint4*)(g_oWh + k*64 + c8*8);
        *(uint4*)(Bl + k*72 + c8*8) = *(const uint4*)(g_oWl + k*64 + c8*8);
    }
    __syncthreads();

    // GEMM3: out = Hp*outW^T -> Qs
    {
        wmma::fragment<wmma::accumulator,16,16,16,float> fc[4];
        #pragma unroll
        for (int nt = 0; nt < 4; nt++) wmma::fill_fragment(fc[nt], 0.f);
        #pragma unroll
        for (int ks = 0; ks < 4; ks++) {
            wmma::fragment<wmma::matrix_a,16,16,16,__nv_bfloat16,wmma::row_major> fah, fal;
            wmma::load_matrix_sync(fah, Ah + (wid*16)*72 + ks*16, 72);
            wmma::load_matrix_sync(fal, Al + (wid*16)*72 + ks*16, 72);
            #pragma unroll
            for (int nt = 0; nt < 4; nt++) {
                wmma::fragment<wmma::matrix_b,16,16,16,__nv_bfloat16,wmma::row_major> fbh, fbl;
                wmma::load_matrix_sync(fbh, Bh + (ks*16)*72 + nt*16, 72);
                wmma::load_matrix_sync(fbl, Bl + (ks*16)*72 + nt*16, 72);
                wmma::mma_sync(fc[nt], fah, fbh, fc[nt]);
                wmma::mma_sync(fc[nt], fah, fbl, fc[nt]);
                wmma::mma_sync(fc[nt], fal, fbh, fc[nt]);
            }
        }
        #pragma unroll
        for (int nt = 0; nt < 4; nt++)
            wmma::store_matrix_sync(Qs + (wid*16)*68 + nt*16, fc[nt], 68, wmma::mem_row_major);
    }
    __syncthreads();

    // LN (bias outb folded in) -> emit bf16 split of H'
    if (tid < 128) {
        float s = 0.f;
        for (int c = 0; c < 64; c++) s += Qs[tid*68 + c] + outb[c];
        float mu = s * (1.f/64.f);
        float v = 0.f;
        for (int c = 0; c < 64; c++) { float d_ = Qs[tid*68 + c] + outb[c] - mu; v += d_*d_; }
        rmean[tid] = mu;
        rinv[tid]  = rsqrtf(v*(1.f/64.f) + 1e-5f);
    }
    __syncthreads();
    #pragma unroll
    for (int j = 0; j < 32; j++) {
        int idx = tid + 256*j;
        int r = idx >> 6, c = idx & 63;
        float v = (Qs[r*68 + c] + outb[c] - rmean[r]) * rinv[r] * lng[c] + lnb[c];
        __nv_bfloat16 h, l; bf16_split(v, h, l);
        size_t go = (size_t)(row0 + r)*64 + c;
        g_Xh[0][go] = h; g_Xl[0][go] = l;
    }
}

// ====== A_dynamic logits via WMMA: S = mv.mv^T / 8, 128x128 tiles ==========
#define MVS_SMEM (4*128*72*2)   // 73728 B

__global__ void __launch_bounds__(256)
k_mvS(float* __restrict__ Sout) {
    extern __shared__ __align__(16) __nv_bfloat16 smb[];
    __nv_bfloat16* Ah = smb;
    __nv_bfloat16* Al = Ah + 128*72;
    __nv_bfloat16* Bh = Al + 128*72;
    __nv_bfloat16* Bl = Bh + 128*72;
    int tid = threadIdx.x, wid = tid >> 5;
    int i0 = blockIdx.x*128, j0 = blockIdx.y*128, b = blockIdx.z;
    const __nv_bfloat16* mh = g_mvh + (size_t)b*NN*64;
    const __nv_bfloat16* ml = g_mvl + (size_t)b*NN*64;
    #pragma unroll
    for (int j = 0; j < 4; j++) {
        int idx = tid + 256*j;      // uint4 over 1024
        int r = idx >> 3, c8 = idx & 7;
        *(uint4*)(Ah + r*72 + c8*8) = *(const uint4*)(mh + (size_t)(i0+r)*64 + c8*8);
        *(uint4*)(Al + r*72 + c8*8) = *(const uint4*)(ml + (size_t)(i0+r)*64 + c8*8);
        *(uint4*)(Bh + r*72 + c8*8) = *(const uint4*)(mh + (size_t)(j0+r)*64 + c8*8);
        *(uint4*)(Bl + r*72 + c8*8) = *(const uint4*)(ml + (size_t)(j0+r)*64 + c8*8);
    }
    __syncthreads();
    wmma::fragment<wmma::accumulator,16,16,16,float> fc[8];
    #pragma unroll
    for (int nt = 0; nt < 8; nt++) wmma::fill_fragment(fc[nt], 0.f);
    #pragma unroll
    for (int ks = 0; ks < 4; ks++) {
        wmma::fragment<wmma::matrix_a,16,16,16,__nv_bfloat16,wmma::row_major> fah, fal;
        wmma::load_matrix_sync(fah, Ah + (wid*16)*72 + ks*16, 72);
        wmma::load_matrix_sync(fal, Al + (wid*16)*72 + ks*16, 72);
        #pragma unroll
        for (int nt = 0; nt < 8; nt++) {
            wmma::fragment<wmma::matrix_b,16,16,16,__nv_bfloat16,wmma::col_major> fbh, fbl;
            wmma::load_matrix_sync(fbh, Bh + (nt*16)*72 + ks*16, 72);
            wmma::load_matrix_sync(fbl, Bl + (nt*16)*72 + ks*16, 72);
            wmma::mma_sync(fc[nt], fah, fbh, fc[nt]);
            wmma::mma_sync(fc[nt], fah, fbl, fc[nt]);
            wmma::mma_sync(fc[nt], fal, fbh, fc[nt]);
        }
    }
    float* Sp = Sout + (size_t)b*NN*NN;
    #pragma unroll
    for (int nt = 0; nt < 8; nt++) {
        #pragma unroll
        for (int i = 0; i < fc[nt].num_elements; i++) fc[nt].x[i] *= 0.125f;
        wmma::store_matrix_sync(Sp + (size_t)(i0 + wid*16)*NN + j0 + nt*16, fc[nt], NN, wmma::mem_row_major);
    }
}

// -------- in-place softmax + fuse + bf16-split emit of A_fused -------------
__global__ void k_softfuse(float* __restrict__ Adyn, float* __restrict__ Afus,
                           const float* __restrict__ Ast, const float* __restrict__ beta) {
    __shared__ float red[256];
    int n = blockIdx.x, b = blockIdx.y, t = threadIdx.x;
    float* Sr = Adyn + ((size_t)b*NN + n)*NN;
    float v[4];
    float mx = -1e30f;
    #pragma unroll
    for (int q = 0; q < 4; q++) { v[q] = Sr[t + q*256]; mx = fmaxf(mx, v[q]); }
    red[t] = mx; __syncthreads();
    for (int o = 128; o > 0; o >>= 1) { if (t < o) red[t] = fmaxf(red[t], red[t+o]); __syncthreads(); }
    mx = red[0]; __syncthreads();
    float s = 0.f;
    #pragma unroll
    for (int q = 0; q < 4; q++) { v[q] = expf(v[q] - mx); s += v[q]; }
    red[t] = s; __syncthreads();
    for (int o = 128; o > 0; o >>= 1) { if (t < o) red[t] += red[t+o]; __syncthreads(); }
    float inv = 1.f / red[0];
    float bta = fminf(fmaxf(beta[0], 0.f), 1.f);
    float din = g_dinv[n];
    float* Fr = Afus + ((size_t)b*NN + n)*NN;
    size_t arow = ((size_t)b*NN + n)*NN;
    #pragma unroll
    for (int q = 0; q < 4; q++) {
        int j = t + q*256;
        float p = v[q] * inv;
        Sr[j] = p;
        float f = bta*p + (1.f - bta) * din * g_dinv[j] * Ast[(size_t)n*NN + j];
        Fr[j] = f;
        __nv_bfloat16 h, l; bf16_split(f, h, l);
        g_Ah[arow + j] = h; g_Al[arow + j] = l;
    }
}

// ===== diffusion hop via WMMA bf16 (pure-bf16 loads, 3-product split) ======
#define A_LD 72
#define DIFF_SMEM ((2*128*A_LD + 2*64*A_LD) * 2)

__global__ void __launch_bounds__(256)
k_diff_wmma(int hop) {
    extern __shared__ __align__(16) __nv_bfloat16 smb[];
    __nv_bfloat16* Ahs = smb;
    __nv_bfloat16* Als = Ahs + 128*A_LD;
    __nv_bfloat16* Bhs = Als + 128*A_LD;
    __nv_bfloat16* Bls = Bhs + 64*A_LD;

    const __nv_bfloat16* Bh_g = g_Xh[hop];
    const __nv_bfloat16* Bl_g = g_Xl[hop];
    __nv_bfloat16* Oh_g = g_Xh[hop + 1];
    __nv_bfloat16* Ol_g = g_Xl[hop + 1];

    int tid = threadIdx.x;
    int wid = tid >> 5;

    int i0 = blockIdx.x * 128;
    int bt = blockIdx.y;
    int b  = bt / NT;
    const __nv_bfloat16* Ah_g = g_Ah + (size_t)b*NN*NN + (size_t)i0*NN;
    const __nv_bfloat16* Al_g = g_Al + (size_t)b*NN*NN + (size_t)i0*NN;
    const __nv_bfloat16* Xh_g = Bh_g + (size_t)bt*NN*64;
    const __nv_bfloat16* Xl_g = Bl_g + (size_t)bt*NN*64;

    wmma::fragment<wmma::accumulator, 16, 16, 16, float> facc[4];
    #pragma unroll
    for (int nt = 0; nt < 4; nt++) wmma::fill_fragment(facc[nt], 0.0f);

    for (int kt = 0; kt < 16; kt++) {
        #pragma unroll
        for (int j = 0; j < 4; j++) {
            int idx = tid + 256*j;
            int r = idx >> 3, c8 = idx & 7;
            size_t go = (size_t)r*NN + kt*64 + c8*8;
            ((uint4*)Ahs)[r*9 + c8] = *(const uint4*)(Ah_g + go);
            ((uint4*)Als)[r*9 + c8] = *(const uint4*)(Al_g + go);
        }
        #pragma unroll
        for (int j = 0; j < 2; j++) {
            int idx = tid + 256*j;
            int k = idx >> 3, c8 = idx & 7;
            size_t go = (size_t)(kt*64 + k)*64 + c8*8;
            ((uint4*)Bhs)[k*9 + c8] = *(const uint4*)(Xh_g + go);
            ((uint4*)Bls)[k*9 + c8] = *(const uint4*)(Xl_g + go);
        }
        __syncthreads();

        #pragma unroll
        for (int ks = 0; ks < 4; ks++) {
            wmma::fragment<wmma::matrix_a, 16, 16, 16, __nv_bfloat16, wmma::row_major> fah, fal;
            wmma::load_matrix_sync(fah, Ahs + (wid*16)*A_LD + ks*16, A_LD);
            wmma::load_matrix_sync(fal, Als + (wid*16)*A_LD + ks*16, A_LD);
            #pragma unroll
            for (int nt = 0; nt < 4; nt++) {
                wmma::fragment<wmma::matrix_b, 16, 16, 16, __nv_bfloat16, wmma::row_major> fbh, fbl;
                wmma::load_matrix_sync(fbh, Bhs + (ks*16)*A_LD + nt*16, A_LD);
                wmma::load_matrix_sync(fbl, Bls + (ks*16)*A_LD + nt*16, A_LD);
                wmma::mma_sync(facc[nt], fah, fbh, facc[nt]);
                wmma::mma_sync(facc[nt], fah, fbl, facc[nt]);
                wmma::mma_sync(facc[nt], fal, fbh, facc[nt]);
            }
        }
        __syncthreads();
    }

    float* Cs = (float*)smb;        // 128*68 fp32 = 34816 B < 55296
    #pragma unroll
    for (int nt = 0; nt < 4; nt++)
        wmma::store_matrix_sync(Cs + (wid*16)*68 + nt*16, facc[nt], 68, wmma::mem_row_major);
    __syncthreads();
    #pragma unroll
    for (int j = 0; j < 32; j++) {
        int idx = tid + 256*j;
        int r = idx >> 6, c = idx & 63;
        float v = Cs[r*68 + c];
        __nv_bfloat16 h, l; bf16_split(v, h, l);
        size_t go = ((size_t)bt*NN + i0 + r)*64 + c;
        Oh_g[go] = h; Ol_g[go] = l;
    }
}

// ====== projection via WMMA (K=192 in 3 chunks from bf16 splits) + LN ======
__global__ void __launch_bounds__(256)
k_proj(const float* __restrict__ pb,
       const float* __restrict__ lng, const float* __restrict__ lnb,
       float* __restrict__ Out) {
    extern __shared__ __align__(16) __nv_bfloat16 smb[];
    __nv_bfloat16* Ahs = smb;
    __nv_bfloat16* Als = Ahs + 128*A_LD;
    __nv_bfloat16* Bhs = Als + 128*A_LD;
    __nv_bfloat16* Bls = Bhs + 64*A_LD;

    int tid = threadIdx.x;
    int wid = tid >> 5;
    int row0 = blockIdx.x * 128;

    wmma::fragment<wmma::accumulator, 16, 16, 16, float> facc[4];
    #pragma unroll
    for (int nt = 0; nt < 4; nt++) wmma::fill_fragment(facc[nt], 0.0f);

    #pragma unroll
    for (int kt = 0; kt < 3; kt++) {
        const __nv_bfloat16* Sh = g_Xh[kt];
        const __nv_bfloat16* Sl = g_Xl[kt];
        #pragma unroll
        for (int j = 0; j < 4; j++) {
            int idx = tid + 256*j;
            int r = idx >> 3, c8 = idx & 7;
            size_t go = (size_t)(row0 + r)*64 + c8*8;
            ((uint4*)Ahs)[r*9 + c8] = *(const uint4*)(Sh + go);
            ((uint4*)Als)[r*9 + c8] = *(const uint4*)(Sl + go);
        }
        #pragma unroll
        for (int j = 0; j < 2; j++) {
            int idx = tid + 256*j;
            int k = idx >> 3, c8 = idx & 7;
            size_t go = (size_t)kt*4096 + (size_t)k*64 + c8*8;
            ((uint4*)Bhs)[k*9 + c8] = *(const uint4*)(g_pWh + go);
            ((uint4*)Bls)[k*9 + c8] = *(const uint4*)(g_pWl + go);
        }
        __syncthreads();

        #pragma unroll
        for (int ks = 0; ks < 4; ks++) {
            wmma::fragment<wmma::matrix_a, 16, 16, 16, __nv_bfloat16, wmma::row_major> fah, fal;
            wmma::load_matrix_sync(fah, Ahs + (wid*16)*A_LD + ks*16, A_LD);
            wmma::load_matrix_sync(fal, Als + (wid*16)*A_LD + ks*16, A_LD);
            #pragma unroll
            for (int nt = 0; nt < 4; nt++) {
                wmma::fragment<wmma::matrix_b, 16, 16, 16, __nv_bfloat16, wmma::row_major> fbh, fbl;
                wmma::load_matrix_sync(fbh, Bhs + (ks*16)*A_LD + nt*16, A_LD);
                wmma::load_matrix_sync(fbl, Bls + (ks*16)*A_LD + nt*16, A_LD);
                wmma::mma_sync(facc[nt], fah, fbh, facc[nt]);
                wmma::mma_sync(facc[nt], fah, fbl, facc[nt]);
                wmma::mma_sync(facc[nt], fal, fbh, facc[nt]);
            }
        }
        __syncthreads();
    }

    float* Cs = (float*)smb;
    float* rmean = Cs + 128*68;
    float* rinv  = rmean + 128;
    #pragma unroll
    for (int nt = 0; nt < 4; nt++)
        wmma::store_matrix_sync(Cs + (wid*16)*68 + nt*16, facc[nt], 68, wmma::mem_row_major);
    __syncthreads();
    if (tid < 128) {
        float s = 0.f;
        for (int c = 0; c < 64; c++) s += Cs[tid*68 + c] + pb[c];
        float mu = s * (1.f/64.f);
        float v = 0.f;
        for (int c = 0; c < 64; c++) { float d_ = Cs[tid*68 + c] + pb[c] - mu; v += d_*d_; }
        rmean[tid] = mu;
        rinv[tid]  = rsqrtf(v*(1.f/64.f) + 1e-5f);
    }
    __syncthreads();
    #pragma unroll
    for (int j = 0; j < 32; j++) {
        int idx = tid + 256*j;
        int r = idx >> 6, c = idx & 63;
        float v = (Cs[r*68 + c] + pb[c] - rmean[r]) * rinv[r] * lng[c] + lnb[c];
        Out[(size_t)(row0 + r)*64 + c] = v;
    }
}

// ---------------- launch ----------------------------------------------------
extern "C" void kernel_launch(void* const* d_in, const int* in_sizes, int n_in,
                              void* d_out, int out_size) {
    const float* H    = (const float*)d_in[0];
    const float* Ast  = (const float*)d_in[1];
    const float* WQ   = (const float*)d_in[2];
    const float* WK   = (const float*)d_in[3];
    const float* WV   = (const float*)d_in[4];
    const float* PHI  = (const float*)d_in[5];
    const float* outW = (const float*)d_in[6];
    const float* outb = (const float*)d_in[7];
    const float* smag = (const float*)d_in[8];
    const float* smab = (const float*)d_in[9];
    const float* beta = (const float*)d_in[10];
    const float* pW   = (const float*)d_in[11];
    const float* pb   = (const float*)d_in[12];
    const float* agg  = (const float*)d_in[13];
    const float* agb  = (const float*)d_in[14];

    float* out  = (float*)d_out;
    float* Hsp  = out;                                    // [B,T,N,D]
    float* Adyn = out + (size_t)ROWS_TOT*64;              // [B,N,N]
    float* Afus = Adyn + (size_t)NB*NN*NN;                // [B,N,N]

    cudaFuncSetAttribute(k_attn, cudaFuncAttributeMaxDynamicSharedMemorySize, ATTN_SMEM);
    cudaFuncSetAttribute(k_mvS, cudaFuncAttributeMaxDynamicSharedMemorySize, MVS_SMEM);
    cudaFuncSetAttribute(k_diff_wmma, cudaFuncAttributeMaxDynamicSharedMemorySize, DIFF_SMEM);
    cudaFuncSetAttribute(k_proj, cudaFuncAttributeMaxDynamicSharedMemorySize, DIFF_SMEM);

    k_pre<<<1, 256>>>(PHI, WK, WV, WQ, outW, pW);
    k_deg<<<NN, 256>>>(Ast);
    k_zero<<<(NB*NN*ND + 255)/256, 256>>>();
    k_attn<<<ROWS_TOT/128, 256, ATTN_SMEM>>>(H, outb, smag, smab);
    k_splitmv<<<NB*NN*ND/4/256, 256>>>();
    dim3 gS(8, 8, NB);
    k_mvS<<<gS, 256, MVS_SMEM>>>(Adyn);
    dim3 gF(NN, NB);
    k_softfuse<<<gF, 256>>>(Adyn, Afus, Ast, beta);
    dim3 gD(8, NB*NT);
    k_diff_wmma<<<gD, 256, DIFF_SMEM>>>(0);
    k_diff_wmma<<<gD, 256, DIFF_SMEM>>>(1);
    k_proj<<<ROWS_TOT/128, 256, DIFF_SMEM>>>(pb, agg, agb, Hsp);
}

// round 14
// speedup vs baseline: 1.6627x; 1.0544x over previous
#include <cuda_runtime.h>
#include <cuda_bf16.h>
#include <mma.h>
#include <math.h>
#include <cstdint>

using namespace nvcuda;

#define NB 8
#define NT 12
#define NN 1024
#define ND 64
#define NE 64
#define NM 16
#define ROWS_TOT (NB*NT*NN)      // 98304

// ---------------- scratch (device globals; allocation-free rule) ----------
__device__ float g_phiK[NM*NE];          // [m][e]
__device__ float g_V[NM*ND];             // [m][d]
__device__ float g_dinv[NN];
__device__ float g_mv[NB*NN*ND];         // mean over t of mem_val
// bf16 hi/lo split tensors (split once, consumed by wmma GEMMs)
__device__ __nv_bfloat16 g_Ah[(size_t)NB*NN*NN];   // A_fused hi
__device__ __nv_bfloat16 g_Al[(size_t)NB*NN*NN];   // A_fused lo
__device__ __nv_bfloat16 g_Xh[3][(size_t)ROWS_TOT*ND];  // {Hp, X1, X2} hi
__device__ __nv_bfloat16 g_Xl[3][(size_t)ROWS_TOT*ND];  // {Hp, X1, X2} lo
__device__ __nv_bfloat16 g_pWh[3*64*64];  // proj_W^T split, [kt][k][n]
__device__ __nv_bfloat16 g_pWl[3*64*64];
__device__ __nv_bfloat16 g_WQh[64*64];    // WQ^T split [d][e]
__device__ __nv_bfloat16 g_WQl[64*64];
__device__ __nv_bfloat16 g_KtVh[64*64];   // KtV split [e][d]
__device__ __nv_bfloat16 g_KtVl[64*64];
__device__ __nv_bfloat16 g_oWh[64*64];    // outW^T split [d][o]
__device__ __nv_bfloat16 g_oWl[64*64];
__device__ __nv_bfloat16 g_mvh[NB*NN*ND]; // mv split
__device__ __nv_bfloat16 g_mvl[NB*NN*ND];

__device__ __forceinline__ void bf16_split(float a, __nv_bfloat16& h, __nv_bfloat16& l) {
    h = __float2bfloat16(a);
    l = __float2bfloat16(a - __bfloat162float(h));
}

// ---------------- small precompute ----------------------------------------
__global__ void k_pre(const float* __restrict__ PHI, const float* __restrict__ WK,
                      const float* __restrict__ WV, const float* __restrict__ WQ,
                      const float* __restrict__ oW, const float* __restrict__ pW) {
    __shared__ float sK[NM*NE];
    __shared__ float sV[NM*ND];
    int t = threadIdx.x;
    for (int i = t; i < NM*NE; i += 256) {
        int m = i >> 6, de = i & 63;
        float s = 0.f, sv = 0.f;
        for (int j = 0; j < NE; j++) {
            float p = PHI[m*NE + j];
            s  += p * WK[de*NE + j];
            sv += p * WV[de*NE + j];
        }
        float pk = (s > 0.f) ? s + 1.f : expf(s);   // elu+1
        sK[i] = pk; g_phiK[i] = pk;
        sV[i] = sv; g_V[i] = sv;
    }
    __syncthreads();
    for (int i = t; i < NE*ND; i += 256) {          // KtV split, [e][d]
        int e = i >> 6, d = i & 63;
        float s = 0.f;
        #pragma unroll
        for (int m = 0; m < NM; m++) s += sK[m*NE + e] * sV[m*ND + d];
        __nv_bfloat16 h, l; bf16_split(s, h, l);
        g_KtVh[i] = h; g_KtVl[i] = l;
    }
    for (int i = t; i < NE*ND; i += 256) {          // WQ^T split: [d][e]
        int d = i >> 6, e = i & 63;
        __nv_bfloat16 h, l; bf16_split(WQ[e*64 + d], h, l);
        g_WQh[i] = h; g_WQl[i] = l;
    }
    for (int i = t; i < ND*ND; i += 256) {          // outW^T split: [d][o]
        int d = i >> 6, o = i & 63;
        __nv_bfloat16 h, l; bf16_split(oW[o*64 + d], h, l);
        g_oWh[i] = h; g_oWl[i] = l;
    }
    for (int i = t; i < 3*64*64; i += 256) {        // proj_W^T split
        int kt = i >> 12, k = (i >> 6) & 63, n = i & 63;
        __nv_bfloat16 h, l; bf16_split(pW[(size_t)n*192 + kt*64 + k], h, l);
        g_pWh[i] = h; g_pWl[i] = l;
    }
}

__global__ void k_deg(const float* __restrict__ A) {
    __shared__ float red[256];
    int n = blockIdx.x, t = threadIdx.x;
    float s = 0.f;
    for (int j = t; j < NN; j += 256) s += A[(size_t)n*NN + j];
    red[t] = s; __syncthreads();
    for (int o = 128; o > 0; o >>= 1) { if (t < o) red[t] += red[t+o]; __syncthreads(); }
    if (t == 0) g_dinv[n] = rsqrtf(red[0] + 1e-12f);
}

__global__ void k_zero() {
    int i = blockIdx.x*256 + threadIdx.x;
    if (i < NB*NN*ND) g_mv[i] = 0.f;
}

__global__ void k_splitmv() {
    int idx = blockIdx.x*256 + threadIdx.x;  // float4 index over 131072
    float4 v = ((const float4*)g_mv)[idx];
    __nv_bfloat16 h0,l0,h1,l1,h2,l2,h3,l3;
    bf16_split(v.x,h0,l0); bf16_split(v.y,h1,l1);
    bf16_split(v.z,h2,l2); bf16_split(v.w,h3,l3);
    int base = idx*4;
    *(__nv_bfloat162*)(g_mvh+base)   = __nv_bfloat162{h0,h1};
    *(__nv_bfloat162*)(g_mvh+base+2) = __nv_bfloat162{h2,h3};
    *(__nv_bfloat162*)(g_mvl+base)   = __nv_bfloat162{l0,l1};
    *(__nv_bfloat162*)(g_mvl+base+2) = __nv_bfloat162{l2,l3};
}

// ====== fused attention via WMMA: 128-row tiles, 256 threads ===============
// smem total 109,568 B; launch_bounds(256,2) caps regs at 128 so 2 CTAs/SM fit.
#define ATTN_SMEM ((2*128*72 + 2*64*72)*2 + (128*68 + 128*20 + 1024 + 1024 + 256)*4)

__global__ void __launch_bounds__(256, 2)
k_attn(const float* __restrict__ H, const float* __restrict__ outb,
       const float* __restrict__ lng, const float* __restrict__ lnb) {
    extern __shared__ __align__(16) __nv_bfloat16 smb[];
    __nv_bfloat16* Ah = smb;
    __nv_bfloat16* Al = Ah + 128*72;
    __nv_bfloat16* Bh = Al + 128*72;
    __nv_bfloat16* Bl = Bh + 64*72;
    float* Qs    = (float*)(Bl + 64*72);
    float* QKs   = Qs + 128*68;
    float* phiKs = QKs + 128*20;
    float* Vs    = phiKs + 1024;
    float* rmean = Vs + 1024;
    float* rinv  = rmean + 128;

    int tid = threadIdx.x, wid = tid >> 5;
    int row0 = blockIdx.x * 128;
    const float* Hb = H + (size_t)row0 * 64;

    // load: H split -> Ah/Al ; WQ^T splits -> Bh/Bl ; phiK, V
    #pragma unroll
    for (int j = 0; j < 8; j++) {
        int idx = tid + 256*j;             // float4 over 2048
        int r = idx >> 4, c4 = idx & 15;
        float4 v = *(const float4*)(Hb + idx*4);
        __nv_bfloat16 h0,l0,h1,l1,h2,l2,h3,l3;
        bf16_split(v.x,h0,l0); bf16_split(v.y,h1,l1);
        bf16_split(v.z,h2,l2); bf16_split(v.w,h3,l3);
        int base = r*72 + c4*4;
        *(__nv_bfloat162*)(Ah+base)   = __nv_bfloat162{h0,h1};
        *(__nv_bfloat162*)(Ah+base+2) = __nv_bfloat162{h2,h3};
        *(__nv_bfloat162*)(Al+base)   = __nv_bfloat162{l0,l1};
        *(__nv_bfloat162*)(Al+base+2) = __nv_bfloat162{l2,l3};
    }
    #pragma unroll
    for (int j = 0; j < 2; j++) {
        int idx = tid + 256*j;             // uint4 over 512
        int k = idx >> 3, c8 = idx & 7;
        *(uint4*)(Bh + k*72 + c8*8) = *(const uint4*)(g_WQh + k*64 + c8*8);
        *(uint4*)(Bl + k*72 + c8*8) = *(const uint4*)(g_WQl + k*64 + c8*8);
    }
    for (int l = tid; l < 1024; l += 256) { phiKs[l] = g_phiK[l]; Vs[l] = g_V[l]; }
    __syncthreads();

    // GEMM1: Q = H*WQ^T ; elu+1 elementwise on fragments ; -> Qs (phiQ fp32)
    {
        wmma::fragment<wmma::accumulator,16,16,16,float> fc[4];
        #pragma unroll
        for (int nt = 0; nt < 4; nt++) wmma::fill_fragment(fc[nt], 0.f);
        #pragma unroll
        for (int ks = 0; ks < 4; ks++) {
            wmma::fragment<wmma::matrix_a,16,16,16,__nv_bfloat16,wmma::row_major> fah, fal;
            wmma::load_matrix_sync(fah, Ah + (wid*16)*72 + ks*16, 72);
            wmma::load_matrix_sync(fal, Al + (wid*16)*72 + ks*16, 72);
            #pragma unroll
            for (int nt = 0; nt < 4; nt++) {
                wmma::fragment<wmma::matrix_b,16,16,16,__nv_bfloat16,wmma::row_major> fbh, fbl;
                wmma::load_matrix_sync(fbh, Bh + (ks*16)*72 + nt*16, 72);
                wmma::load_matrix_sync(fbl, Bl + (ks*16)*72 + nt*16, 72);
                wmma::mma_sync(fc[nt], fah, fbh, fc[nt]);
                wmma::mma_sync(fc[nt], fah, fbl, fc[nt]);
                wmma::mma_sync(fc[nt], fal, fbh, fc[nt]);
            }
        }
        #pragma unroll
        for (int nt = 0; nt < 4; nt++) {
            #pragma unroll
            for (int i = 0; i < fc[nt].num_elements; i++) {
                float q = fc[nt].x[i];
                fc[nt].x[i] = (q > 0.f) ? q + 1.f : expf(q);
            }
            wmma::store_matrix_sync(Qs + (wid*16)*68 + nt*16, fc[nt], 68, wmma::mem_row_major);
        }
    }
    __syncthreads();

    // split phiQ -> Ah/Al ; Bh/Bl <- KtV splits ; QK from Qs
    #pragma unroll
    for (int j = 0; j < 32; j++) {
        int idx = tid + 256*j;
        int r = idx >> 6, c = idx & 63;
        __nv_bfloat16 h, l; bf16_split(Qs[r*68 + c], h, l);
        Ah[r*72 + c] = h; Al[r*72 + c] = l;
    }
    #pragma unroll
    for (int j = 0; j < 2; j++) {
        int idx = tid + 256*j;
        int k = idx >> 3, c8 = idx & 7;
        *(uint4*)(Bh + k*72 + c8*8) = *(const uint4*)(g_KtVh + k*64 + c8*8);
        *(uint4*)(Bl + k*72 + c8*8) = *(const uint4*)(g_KtVl + k*64 + c8*8);
    }
    {
        int r = tid >> 1, mg = tid & 1;
        float s[8] = {};
        for (int e = 0; e < 64; e++) {
            float q = Qs[r*68 + e];
            #pragma unroll
            for (int mm = 0; mm < 8; mm++)
                s[mm] += q * phiKs[(mg*8 + mm)*64 + e];
        }
        #pragma unroll
        for (int mm = 0; mm < 8; mm++) QKs[r*20 + mg*8 + mm] = s[mm] * 0.125f;
    }
    __syncthreads();

    // softmax over M=16 per row
    if (tid < 128) {
        float mx = -1e30f;
        #pragma unroll
        for (int m = 0; m < 16; m++) mx = fmaxf(mx, QKs[tid*20 + m]);
        float ss = 0.f;
        #pragma unroll
        for (int m = 0; m < 16; m++) { float e_ = expf(QKs[tid*20 + m] - mx); QKs[tid*20 + m] = e_; ss += e_; }
        float inv = 1.f / ss;
        #pragma unroll
        for (int m = 0; m < 16; m++) QKs[tid*20 + m] *= inv;
    }
    __syncthreads();

    // mem_val -> mv (mean over t via atomic)
    {
        int r = tid >> 1, dq = tid & 1;
        int grow = row0 + r;
        int b_ = grow / (NT*NN);
        int n_ = grow & (NN - 1);
        float am[16];
        #pragma unroll
        for (int m = 0; m < 16; m++) am[m] = QKs[r*20 + m];
        float* mvp = g_mv + ((size_t)(b_*NN + n_))*64 + dq*32;
        #pragma unroll
        for (int dd = 0; dd < 32; dd++) {
            float s = 0.f;
            #pragma unroll
            for (int m = 0; m < 16; m++) s += am[m] * Vs[m*64 + dq*32 + dd];
            atomicAdd(mvp + dd, s * (1.f/NT));
        }
    }

    // GEMM2: main_att = phiQ*KtV -> Qs
    {
        wmma::fragment<wmma::accumulator,16,16,16,float> fc[4];
        #pragma unroll
        for (int nt = 0; nt < 4; nt++) wmma::fill_fragment(fc[nt], 0.f);
        #pragma unroll
        for (int ks = 0; ks < 4; ks++) {
            wmma::fragment<wmma::matrix_a,16,16,16,__nv_bfloat16,wmma::row_major> fah, fal;
            wmma::load_matrix_sync(fah, Ah + (wid*16)*72 + ks*16, 72);
            wmma::load_matrix_sync(fal, Al + (wid*16)*72 + ks*16, 72);
            #pragma unroll
            for (int nt = 0; nt < 4; nt++) {
                wmma::fragment<wmma::matrix_b,16,16,16,__nv_bfloat16,wmma::row_major> fbh, fbl;
                wmma::load_matrix_sync(fbh, Bh + (ks*16)*72 + nt*16, 72);
                wmma::load_matrix_sync(fbl, Bl + (ks*16)*72 + nt*16, 72);
                wmma::mma_sync(fc[nt], fah, fbh, fc[nt]);
                wmma::mma_sync(fc[nt], fah, fbl, fc[nt]);
                wmma::mma_sync(fc[nt], fal, fbh, fc[nt]);
            }
        }
        #pragma unroll
        for (int nt = 0; nt < 4; nt++)
            wmma::store_matrix_sync(Qs + (wid*16)*68 + nt*16, fc[nt], 68, wmma::mem_row_major);
    }
    __syncthreads();

    // Hp = main + H (H reloaded from gmem) ; split -> Ah/Al ; Bh/Bl <- outW^T
    #pragma unroll
    for (int j = 0; j < 32; j++) {
        int idx = tid + 256*j;
        int r = idx >> 6, c = idx & 63;
        float v = Qs[r*68 + c] + Hb[idx];
        __nv_bfloat16 h, l; bf16_split(v, h, l);
        Ah[r*72 + c] = h; Al[r*72 + c] = l;
    }
    #pragma unroll
    for (int j = 0; j < 2; j++) {
        int idx = tid + 256*j;
        int k = idx >> 3, c8 = idx & 7;
        *(uint4*)(Bh + k*72 + c8*8) = *(const uint4*)(g_oWh + k*64 + c8*8);
        *(uint4*)(Bl + k*72 + c8*8) = *(const uint4*)(g_oWl + k*64 + c8*8);
    }
    __syncthreads();

    // GEMM3: out = Hp*outW^T -> Qs
    {
        wmma::fragment<wmma::accumulator,16,16,16,float> fc[4];
        #pragma unroll
        for (int nt = 0; nt < 4; nt++) wmma::fill_fragment(fc[nt], 0.f);
        #pragma unroll
        for (int ks = 0; ks < 4; ks++) {
            wmma::fragment<wmma::matrix_a,16,16,16,__nv_bfloat16,wmma::row_major> fah, fal;
            wmma::load_matrix_sync(fah, Ah + (wid*16)*72 + ks*16, 72);
            wmma::load_matrix_sync(fal, Al + (wid*16)*72 + ks*16, 72);
            #pragma unroll
            for (int nt = 0; nt < 4; nt++) {
                wmma::fragment<wmma::matrix_b,16,16,16,__nv_bfloat16,wmma::row_major> fbh, fbl;
                wmma::load_matrix_sync(fbh, Bh + (ks*16)*72 + nt*16, 72);
                wmma::load_matrix_sync(fbl, Bl + (ks*16)*72 + nt*16, 72);
                wmma::mma_sync(fc[nt], fah, fbh, fc[nt]);
                wmma::mma_sync(fc[nt], fah, fbl, fc[nt]);
                wmma::mma_sync(fc[nt], fal, fbh, fc[nt]);
            }
        }
        #pragma unroll
        for (int nt = 0; nt < 4; nt++)
            wmma::store_matrix_sync(Qs + (wid*16)*68 + nt*16, fc[nt], 68, wmma::mem_row_major);
    }
    __syncthreads();

    // LN (bias outb folded in) -> emit bf16 split of H'
    if (tid < 128) {
        float s = 0.f;
        for (int c = 0; c < 64; c++) s += Qs[tid*68 + c] + outb[c];
        float mu = s * (1.f/64.f);
        float v = 0.f;
        for (int c = 0; c < 64; c++) { float d_ = Qs[tid*68 + c] + outb[c] - mu; v += d_*d_; }
        rmean[tid] = mu;
        rinv[tid]  = rsqrtf(v*(1.f/64.f) + 1e-5f);
    }
    __syncthreads();
    #pragma unroll
    for (int j = 0; j < 32; j++) {
        int idx = tid + 256*j;
        int r = idx >> 6, c = idx & 63;
        float v = (Qs[r*68 + c] + outb[c] - rmean[r]) * rinv[r] * lng[c] + lnb[c];
        __nv_bfloat16 h, l; bf16_split(v, h, l);
        size_t go = (size_t)(row0 + r)*64 + c;
        g_Xh[0][go] = h; g_Xl[0][go] = l;
    }
}

// ====== A_dynamic logits via WMMA: S = mv.mv^T / 8, 128x128 tiles ==========
#define MVS_SMEM (4*128*72*2)   // 73728 B

__global__ void __launch_bounds__(256)
k_mvS(float* __restrict__ Sout) {
    extern __shared__ __align__(16) __nv_bfloat16 smb[];
    __nv_bfloat16* Ah = smb;
    __nv_bfloat16* Al = Ah + 128*72;
    __nv_bfloat16* Bh = Al + 128*72;
    __nv_bfloat16* Bl = Bh + 128*72;
    int tid = threadIdx.x, wid = tid >> 5;
    int i0 = blockIdx.x*128, j0 = blockIdx.y*128, b = blockIdx.z;
    const __nv_bfloat16* mh = g_mvh + (size_t)b*NN*64;
    const __nv_bfloat16* ml = g_mvl + (size_t)b*NN*64;
    #pragma unroll
    for (int j = 0; j < 4; j++) {
        int idx = tid + 256*j;      // uint4 over 1024
        int r = idx >> 3, c8 = idx & 7;
        *(uint4*)(Ah + r*72 + c8*8) = *(const uint4*)(mh + (size_t)(i0+r)*64 + c8*8);
        *(uint4*)(Al + r*72 + c8*8) = *(const uint4*)(ml + (size_t)(i0+r)*64 + c8*8);
        *(uint4*)(Bh + r*72 + c8*8) = *(const uint4*)(mh + (size_t)(j0+r)*64 + c8*8);
        *(uint4*)(Bl + r*72 + c8*8) = *(const uint4*)(ml + (size_t)(j0+r)*64 + c8*8);
    }
    __syncthreads();
    wmma::fragment<wmma::accumulator,16,16,16,float> fc[8];
    #pragma unroll
    for (int nt = 0; nt < 8; nt++) wmma::fill_fragment(fc[nt], 0.f);
    #pragma unroll
    for (int ks = 0; ks < 4; ks++) {
        wmma::fragment<wmma::matrix_a,16,16,16,__nv_bfloat16,wmma::row_major> fah, fal;
        wmma::load_matrix_sync(fah, Ah + (wid*16)*72 + ks*16, 72);
        wmma::load_matrix_sync(fal, Al + (wid*16)*72 + ks*16, 72);
        #pragma unroll
        for (int nt = 0; nt < 8; nt++) {
            wmma::fragment<wmma::matrix_b,16,16,16,__nv_bfloat16,wmma::col_major> fbh, fbl;
            wmma::load_matrix_sync(fbh, Bh + (nt*16)*72 + ks*16, 72);
            wmma::load_matrix_sync(fbl, Bl + (nt*16)*72 + ks*16, 72);
            wmma::mma_sync(fc[nt], fah, fbh, fc[nt]);
            wmma::mma_sync(fc[nt], fah, fbl, fc[nt]);
            wmma::mma_sync(fc[nt], fal, fbh, fc[nt]);
        }
    }
    float* Sp = Sout + (size_t)b*NN*NN;
    #pragma unroll
    for (int nt = 0; nt < 8; nt++) {
        #pragma unroll
        for (int i = 0; i < fc[nt].num_elements; i++) fc[nt].x[i] *= 0.125f;
        wmma::store_matrix_sync(Sp + (size_t)(i0 + wid*16)*NN + j0 + nt*16, fc[nt], NN, wmma::mem_row_major);
    }
}

// -------- in-place softmax + fuse + bf16-split emit of A_fused -------------
__global__ void k_softfuse(float* __restrict__ Adyn, float* __restrict__ Afus,
                           const float* __restrict__ Ast, const float* __restrict__ beta) {
    __shared__ float red[256];
    int n = blockIdx.x, b = blockIdx.y, t = threadIdx.x;
    float* Sr = Adyn + ((size_t)b*NN + n)*NN;
    float v[4];
    float mx = -1e30f;
    #pragma unroll
    for (int q = 0; q < 4; q++) { v[q] = Sr[t + q*256]; mx = fmaxf(mx, v[q]); }
    red[t] = mx; __syncthreads();
    for (int o = 128; o > 0; o >>= 1) { if (t < o) red[t] = fmaxf(red[t], red[t+o]); __syncthreads(); }
    mx = red[0]; __syncthreads();
    float s = 0.f;
    #pragma unroll
    for (int q = 0; q < 4; q++) { v[q] = expf(v[q] - mx); s += v[q]; }
    red[t] = s; __syncthreads();
    for (int o = 128; o > 0; o >>= 1) { if (t < o) red[t] += red[t+o]; __syncthreads(); }
    float inv = 1.f / red[0];
    float bta = fminf(fmaxf(beta[0], 0.f), 1.f);
    float din = g_dinv[n];
    float* Fr = Afus + ((size_t)b*NN + n)*NN;
    size_t arow = ((size_t)b*NN + n)*NN;
    #pragma unroll
    for (int q = 0; q < 4; q++) {
        int j = t + q*256;
        float p = v[q] * inv;
        Sr[j] = p;
        float f = bta*p + (1.f - bta) * din * g_dinv[j] * Ast[(size_t)n*NN + j];
        Fr[j] = f;
        __nv_bfloat16 h, l; bf16_split(f, h, l);
        g_Ah[arow + j] = h; g_Al[arow + j] = l;
    }
}

// ===== diffusion hop via WMMA bf16: 2 t-blocks per CTA (A reuse) ===========
// smem: Ah/Al 128*72 + B{0,1}{h,l} 64*72 each = 73,728 B -> 2 CTA/SM.
#define A_LD 72
#define DIFF_SMEM ((2*128*A_LD + 4*64*A_LD) * 2)

__global__ void __launch_bounds__(256, 2)
k_diff_wmma(int hop) {
    extern __shared__ __align__(16) __nv_bfloat16 smb[];
    __nv_bfloat16* Ahs = smb;
    __nv_bfloat16* Als = Ahs + 128*A_LD;
    __nv_bfloat16* B0h = Als + 128*A_LD;
    __nv_bfloat16* B0l = B0h + 64*A_LD;
    __nv_bfloat16* B1h = B0l + 64*A_LD;
    __nv_bfloat16* B1l = B1h + 64*A_LD;

    int tid = threadIdx.x;
    int wid = tid >> 5;

    int i0 = blockIdx.x * 128;
    int bt0 = blockIdx.y * 2;          // NT=12 even => both t in same batch
    int b  = bt0 / NT;
    const __nv_bfloat16* Ah_g = g_Ah + (size_t)b*NN*NN + (size_t)i0*NN;
    const __nv_bfloat16* Al_g = g_Al + (size_t)b*NN*NN + (size_t)i0*NN;
    const __nv_bfloat16* X0h = g_Xh[hop] + (size_t)bt0*NN*64;
    const __nv_bfloat16* X0l = g_Xl[hop] + (size_t)bt0*NN*64;
    const __nv_bfloat16* X1h = X0h + (size_t)NN*64;
    const __nv_bfloat16* X1l = X0l + (size_t)NN*64;

    wmma::fragment<wmma::accumulator, 16, 16, 16, float> facc[2][4];
    #pragma unroll
    for (int tt = 0; tt < 2; tt++)
        #pragma unroll
        for (int nt = 0; nt < 4; nt++) wmma::fill_fragment(facc[tt][nt], 0.0f);

    for (int kt = 0; kt < 16; kt++) {
        #pragma unroll
        for (int j = 0; j < 4; j++) {
            int idx = tid + 256*j;
            int r = idx >> 3, c8 = idx & 7;
            size_t go = (size_t)r*NN + kt*64 + c8*8;
            ((uint4*)Ahs)[r*9 + c8] = *(const uint4*)(Ah_g + go);
            ((uint4*)Als)[r*9 + c8] = *(const uint4*)(Al_g + go);
        }
        #pragma unroll
        for (int j = 0; j < 2; j++) {
            int idx = tid + 256*j;
            int k = idx >> 3, c8 = idx & 7;
            size_t go = (size_t)(kt*64 + k)*64 + c8*8;
            ((uint4*)B0h)[k*9 + c8] = *(const uint4*)(X0h + go);
            ((uint4*)B0l)[k*9 + c8] = *(const uint4*)(X0l + go);
            ((uint4*)B1h)[k*9 + c8] = *(const uint4*)(X1h + go);
            ((uint4*)B1l)[k*9 + c8] = *(const uint4*)(X1l + go);
        }
        __syncthreads();

        #pragma unroll
        for (int ks = 0; ks < 4; ks++) {
            wmma::fragment<wmma::matrix_a, 16, 16, 16, __nv_bfloat16, wmma::row_major> fah, fal;
            wmma::load_matrix_sync(fah, Ahs + (wid*16)*A_LD + ks*16, A_LD);
            wmma::load_matrix_sync(fal, Als + (wid*16)*A_LD + ks*16, A_LD);
            #pragma unroll
            for (int tt = 0; tt < 2; tt++) {
                const __nv_bfloat16* Bhp = tt ? B1h : B0h;
                const __nv_bfloat16* Blp = tt ? B1l : B0l;
                #pragma unroll
                for (int nt = 0; nt < 4; nt++) {
                    wmma::fragment<wmma::matrix_b, 16, 16, 16, __nv_bfloat16, wmma::row_major> fbh, fbl;
                    wmma::load_matrix_sync(fbh, Bhp + (ks*16)*A_LD + nt*16, A_LD);
                    wmma::load_matrix_sync(fbl, Blp + (ks*16)*A_LD + nt*16, A_LD);
                    wmma::mma_sync(facc[tt][nt], fah, fbh, facc[tt][nt]);
                    wmma::mma_sync(facc[tt][nt], fah, fbl, facc[tt][nt]);
                    wmma::mma_sync(facc[tt][nt], fal, fbh, facc[tt][nt]);
                }
            }
        }
        __syncthreads();
    }

    // epilogue: per t-block, stage fp32 in aliased smem, split + write bf16
    float* Cs = (float*)smb;        // 128*68 fp32 = 34816 B < 73728
    #pragma unroll
    for (int tt = 0; tt < 2; tt++) {
        #pragma unroll
        for (int nt = 0; nt < 4; nt++)
            wmma::store_matrix_sync(Cs + (wid*16)*68 + nt*16, facc[tt][nt], 68, wmma::mem_row_major);
        __syncthreads();
        __nv_bfloat16* Oh_g = g_Xh[hop + 1] + (size_t)(bt0 + tt)*NN*64;
        __nv_bfloat16* Ol_g = g_Xl[hop + 1] + (size_t)(bt0 + tt)*NN*64;
        #pragma unroll
        for (int j = 0; j < 32; j++) {
            int idx = tid + 256*j;
            int r = idx >> 6, c = idx & 63;
            float v = Cs[r*68 + c];
            __nv_bfloat16 h, l; bf16_split(v, h, l);
            size_t go = (size_t)(i0 + r)*64 + c;
            Oh_g[go] = h; Ol_g[go] = l;
        }
        __syncthreads();
    }
}

// ====== projection via WMMA (K=192 in 3 chunks from bf16 splits) + LN ======
#define PROJ_SMEM ((2*128*A_LD + 2*64*A_LD) * 2)

__global__ void __launch_bounds__(256)
k_proj(const float* __restrict__ pb,
       const float* __restrict__ lng, const float* __restrict__ lnb,
       float* __restrict__ Out) {
    extern __shared__ __align__(16) __nv_bfloat16 smb[];
    __nv_bfloat16* Ahs = smb;
    __nv_bfloat16* Als = Ahs + 128*A_LD;
    __nv_bfloat16* Bhs = Als + 128*A_LD;
    __nv_bfloat16* Bls = Bhs + 64*A_LD;

    int tid = threadIdx.x;
    int wid = tid >> 5;
    int row0 = blockIdx.x * 128;

    wmma::fragment<wmma::accumulator, 16, 16, 16, float> facc[4];
    #pragma unroll
    for (int nt = 0; nt < 4; nt++) wmma::fill_fragment(facc[nt], 0.0f);

    #pragma unroll
    for (int kt = 0; kt < 3; kt++) {
        const __nv_bfloat16* Sh = g_Xh[kt];
        const __nv_bfloat16* Sl = g_Xl[kt];
        #pragma unroll
        for (int j = 0; j < 4; j++) {
            int idx = tid + 256*j;
            int r = idx >> 3, c8 = idx & 7;
            size_t go = (size_t)(row0 + r)*64 + c8*8;
            ((uint4*)Ahs)[r*9 + c8] = *(const uint4*)(Sh + go);
            ((uint4*)Als)[r*9 + c8] = *(const uint4*)(Sl + go);
        }
        #pragma unroll
        for (int j = 0; j < 2; j++) {
            int idx = tid + 256*j;
            int k = idx >> 3, c8 = idx & 7;
            size_t go = (size_t)kt*4096 + (size_t)k*64 + c8*8;
            ((uint4*)Bhs)[k*9 + c8] = *(const uint4*)(g_pWh + go);
            ((uint4*)Bls)[k*9 + c8] = *(const uint4*)(g_pWl + go);
        }
        __syncthreads();

        #pragma unroll
        for (int ks = 0; ks < 4; ks++) {
            wmma::fragment<wmma::matrix_a, 16, 16, 16, __nv_bfloat16, wmma::row_major> fah, fal;
            wmma::load_matrix_sync(fah, Ahs + (wid*16)*A_LD + ks*16, A_LD);
            wmma::load_matrix_sync(fal, Als + (wid*16)*A_LD + ks*16, A_LD);
            #pragma unroll
            for (int nt = 0; nt < 4; nt++) {
                wmma::fragment<wmma::matrix_b, 16, 16, 16, __nv_bfloat16, wmma::row_major> fbh, fbl;
                wmma::load_matrix_sync(fbh, Bhs + (ks*16)*A_LD + nt*16, A_LD);
                wmma::load_matrix_sync(fbl, Bls + (ks*16)*A_LD + nt*16, A_LD);
                wmma::mma_sync(facc[nt], fah, fbh, facc[nt]);
                wmma::mma_sync(facc[nt], fah, fbl, facc[nt]);
                wmma::mma_sync(facc[nt], fal, fbh, facc[nt]);
            }
        }
        __syncthreads();
    }

    float* Cs = (float*)smb;
    float* rmean = Cs + 128*68;
    float* rinv  = rmean + 128;
    #pragma unroll
    for (int nt = 0; nt < 4; nt++)
        wmma::store_matrix_sync(Cs + (wid*16)*68 + nt*16, facc[nt], 68, wmma::mem_row_major);
    __syncthreads();
    if (tid < 128) {
        float s = 0.f;
        for (int c = 0; c < 64; c++) s += Cs[tid*68 + c] + pb[c];
        float mu = s * (1.f/64.f);
        float v = 0.f;
        for (int c = 0; c < 64; c++) { float d_ = Cs[tid*68 + c] + pb[c] - mu; v += d_*d_; }
        rmean[tid] = mu;
        rinv[tid]  = rsqrtf(v*(1.f/64.f) + 1e-5f);
    }
    __syncthreads();
    #pragma unroll
    for (int j = 0; j < 32; j++) {
        int idx = tid + 256*j;
        int r = idx >> 6, c = idx & 63;
        float v = (Cs[r*68 + c] + pb[c] - rmean[r]) * rinv[r] * lng[c] + lnb[c];
        Out[(size_t)(row0 + r)*64 + c] = v;
    }
}

// ---------------- launch ----------------------------------------------------
extern "C" void kernel_launch(void* const* d_in, const int* in_sizes, int n_in,
                              void* d_out, int out_size) {
    const float* H    = (const float*)d_in[0];
    const float* Ast  = (const float*)d_in[1];
    const float* WQ   = (const float*)d_in[2];
    const float* WK   = (const float*)d_in[3];
    const float* WV   = (const float*)d_in[4];
    const float* PHI  = (const float*)d_in[5];
    const float* outW = (const float*)d_in[6];
    const float* outb = (const float*)d_in[7];
    const float* smag = (const float*)d_in[8];
    const float* smab = (const float*)d_in[9];
    const float* beta = (const float*)d_in[10];
    const float* pW   = (const float*)d_in[11];
    const float* pb   = (const float*)d_in[12];
    const float* agg  = (const float*)d_in[13];
    const float* agb  = (const float*)d_in[14];

    float* out  = (float*)d_out;
    float* Hsp  = out;                                    // [B,T,N,D]
    float* Adyn = out + (size_t)ROWS_TOT*64;              // [B,N,N]
    float* Afus = Adyn + (size_t)NB*NN*NN;                // [B,N,N]

    cudaFuncSetAttribute(k_attn, cudaFuncAttributeMaxDynamicSharedMemorySize, ATTN_SMEM);
    cudaFuncSetAttribute(k_mvS, cudaFuncAttributeMaxDynamicSharedMemorySize, MVS_SMEM);
    cudaFuncSetAttribute(k_diff_wmma, cudaFuncAttributeMaxDynamicSharedMemorySize, DIFF_SMEM);
    cudaFuncSetAttribute(k_proj, cudaFuncAttributeMaxDynamicSharedMemorySize, PROJ_SMEM);

    k_pre<<<1, 256>>>(PHI, WK, WV, WQ, outW, pW);
    k_deg<<<NN, 256>>>(Ast);
    k_zero<<<(NB*NN*ND + 255)/256, 256>>>();
    k_attn<<<ROWS_TOT/128, 256, ATTN_SMEM>>>(H, outb, smag, smab);
    k_splitmv<<<NB*NN*ND/4/256, 256>>>();
    dim3 gS(8, 8, NB);
    k_mvS<<<gS, 256, MVS_SMEM>>>(Adyn);
    dim3 gF(NN, NB);
    k_softfuse<<<gF, 256>>>(Adyn, Afus, Ast, beta);
    dim3 gD(8, NB*NT/2);
    k_diff_wmma<<<gD, 256, DIFF_SMEM>>>(0);
    k_diff_wmma<<<gD, 256, DIFF_SMEM>>>(1);
    k_proj<<<ROWS_TOT/128, 256, PROJ_SMEM>>>(pb, agg, agb, Hsp);
}

// round 16
// speedup vs baseline: 1.7004x; 1.0226x over previous
#include <cuda_runtime.h>
#include <cuda_bf16.h>
#include <mma.h>
#include <math.h>
#include <cstdint>

using namespace nvcuda;

#define NB 8
#define NT 12
#define NN 1024
#define ND 64
#define NE 64
#define NM 16
#define ROWS_TOT (NB*NT*NN)      // 98304

// ---------------- scratch (device globals; allocation-free rule) ----------
__device__ float g_phiK[NM*NE];          // [m][e]
__device__ float g_V[NM*ND];             // [m][d]
__device__ float g_dinv[NN];
__device__ float g_mv[NB*NN*ND];         // mean over t of mem_val
// bf16 hi/lo split tensors (split once, consumed by wmma GEMMs)
__device__ __nv_bfloat16 g_Ah[(size_t)NB*NN*NN];   // A_fused hi
__device__ __nv_bfloat16 g_Al[(size_t)NB*NN*NN];   // A_fused lo
__device__ __nv_bfloat16 g_Xh[3][(size_t)ROWS_TOT*ND];  // {Hp, X1, X2} hi
__device__ __nv_bfloat16 g_Xl[3][(size_t)ROWS_TOT*ND];  // {Hp, X1, X2} lo
__device__ __nv_bfloat16 g_pWh[3*64*64];  // proj_W^T split, [kt][k][n]
__device__ __nv_bfloat16 g_pWl[3*64*64];
__device__ __nv_bfloat16 g_WQh[64*64];    // WQ^T split [d][e]
__device__ __nv_bfloat16 g_WQl[64*64];
__device__ __nv_bfloat16 g_KtVh[64*64];   // KtV split [e][d]
__device__ __nv_bfloat16 g_KtVl[64*64];
__device__ __nv_bfloat16 g_oWh[64*64];    // outW^T split [d][o]
__device__ __nv_bfloat16 g_oWl[64*64];
__device__ __nv_bfloat16 g_mvh[NB*NN*ND]; // mv split
__device__ __nv_bfloat16 g_mvl[NB*NN*ND];

__device__ __forceinline__ void bf16_split(float a, __nv_bfloat16& h, __nv_bfloat16& l) {
    h = __float2bfloat16(a);
    l = __float2bfloat16(a - __bfloat162float(h));
}

__device__ __forceinline__ void cp16(void* smem, const void* gmem) {
    uint32_t s = (uint32_t)__cvta_generic_to_shared(smem);
    asm volatile("cp.async.cg.shared.global [%0], [%1], 16;" :: "r"(s), "l"(gmem));
}
#define CP_COMMIT() asm volatile("cp.async.commit_group;" ::: "memory")
#define CP_WAIT(n)  asm volatile("cp.async.wait_group %0;" :: "n"(n) : "memory")

// ---------------- small precompute ----------------------------------------
__global__ void k_pre(const float* __restrict__ PHI, const float* __restrict__ WK,
                      const float* __restrict__ WV, const float* __restrict__ WQ,
                      const float* __restrict__ oW, const float* __restrict__ pW) {
    __shared__ float sK[NM*NE];
    __shared__ float sV[NM*ND];
    int t = threadIdx.x;
    for (int i = t; i < NM*NE; i += 256) {
        int m = i >> 6, de = i & 63;
        float s = 0.f, sv = 0.f;
        for (int j = 0; j < NE; j++) {
            float p = PHI[m*NE + j];
            s  += p * WK[de*NE + j];
            sv += p * WV[de*NE + j];
        }
        float pk = (s > 0.f) ? s + 1.f : expf(s);   // elu+1
        sK[i] = pk; g_phiK[i] = pk;
        sV[i] = sv; g_V[i] = sv;
    }
    __syncthreads();
    for (int i = t; i < NE*ND; i += 256) {          // KtV split, [e][d]
        int e = i >> 6, d = i & 63;
        float s = 0.f;
        #pragma unroll
        for (int m = 0; m < NM; m++) s += sK[m*NE + e] * sV[m*ND + d];
        __nv_bfloat16 h, l; bf16_split(s, h, l);
        g_KtVh[i] = h; g_KtVl[i] = l;
    }
    for (int i = t; i < NE*ND; i += 256) {          // WQ^T split: [d][e]
        int d = i >> 6, e = i & 63;
        __nv_bfloat16 h, l; bf16_split(WQ[e*64 + d], h, l);
        g_WQh[i] = h; g_WQl[i] = l;
    }
    for (int i = t; i < ND*ND; i += 256) {          // outW^T split: [d][o]
        int d = i >> 6, o = i & 63;
        __nv_bfloat16 h, l; bf16_split(oW[o*64 + d], h, l);
        g_oWh[i] = h; g_oWl[i] = l;
    }
    for (int i = t; i < 3*64*64; i += 256) {        // proj_W^T split
        int kt = i >> 12, k = (i >> 6) & 63, n = i & 63;
        __nv_bfloat16 h, l; bf16_split(pW[(size_t)n*192 + kt*64 + k], h, l);
        g_pWh[i] = h; g_pWl[i] = l;
    }
}

__global__ void k_deg(const float* __restrict__ A) {
    __shared__ float red[256];
    int n = blockIdx.x, t = threadIdx.x;
    float s = 0.f;
    for (int j = t; j < NN; j += 256) s += A[(size_t)n*NN + j];
    red[t] = s; __syncthreads();
    for (int o = 128; o > 0; o >>= 1) { if (t < o) red[t] += red[t+o]; __syncthreads(); }
    if (t == 0) g_dinv[n] = rsqrtf(red[0] + 1e-12f);
}

__global__ void k_zero() {
    int i = blockIdx.x*256 + threadIdx.x;
    if (i < NB*NN*ND) g_mv[i] = 0.f;
}

__global__ void k_splitmv() {
    int idx = blockIdx.x*256 + threadIdx.x;  // float4 index over 131072
    float4 v = ((const float4*)g_mv)[idx];
    __nv_bfloat16 h0,l0,h1,l1,h2,l2,h3,l3;
    bf16_split(v.x,h0,l0); bf16_split(v.y,h1,l1);
    bf16_split(v.z,h2,l2); bf16_split(v.w,h3,l3);
    int base = idx*4;
    *(__nv_bfloat162*)(g_mvh+base)   = __nv_bfloat162{h0,h1};
    *(__nv_bfloat162*)(g_mvh+base+2) = __nv_bfloat162{h2,h3};
    *(__nv_bfloat162*)(g_mvl+base)   = __nv_bfloat162{l0,l1};
    *(__nv_bfloat162*)(g_mvl+base+2) = __nv_bfloat162{l2,l3};
}

// ====== fused attention via WMMA: 128-row tiles, 256 threads ===============
#define ATTN_SMEM ((2*128*72 + 2*64*72)*2 + (128*68 + 128*20 + 1024 + 1024 + 256)*4)

__global__ void __launch_bounds__(256, 2)
k_attn(const float* __restrict__ H, const float* __restrict__ outb,
       const float* __restrict__ lng, const float* __restrict__ lnb) {
    extern __shared__ __align__(16) __nv_bfloat16 smb[];
    __nv_bfloat16* Ah = smb;
    __nv_bfloat16* Al = Ah + 128*72;
    __nv_bfloat16* Bh = Al + 128*72;
    __nv_bfloat16* Bl = Bh + 64*72;
    float* Qs    = (float*)(Bl + 64*72);
    float* QKs   = Qs + 128*68;
    float* phiKs = QKs + 128*20;
    float* Vs    = phiKs + 1024;
    float* rmean = Vs + 1024;
    float* rinv  = rmean + 128;

    int tid = threadIdx.x, wid = tid >> 5;
    int row0 = blockIdx.x * 128;
    const float* Hb = H + (size_t)row0 * 64;

    // load: H split -> Ah/Al ; WQ^T splits -> Bh/Bl ; phiK, V
    #pragma unroll
    for (int j = 0; j < 8; j++) {
        int idx = tid + 256*j;             // float4 over 2048
        int r = idx >> 4, c4 = idx & 15;
        float4 v = *(const float4*)(Hb + idx*4);
        __nv_bfloat16 h0,l0,h1,l1,h2,l2,h3,l3;
        bf16_split(v.x,h0,l0); bf16_split(v.y,h1,l1);
        bf16_split(v.z,h2,l2); bf16_split(v.w,h3,l3);
        int base = r*72 + c4*4;
        *(__nv_bfloat162*)(Ah+base)   = __nv_bfloat162{h0,h1};
        *(__nv_bfloat162*)(Ah+base+2) = __nv_bfloat162{h2,h3};
        *(__nv_bfloat162*)(Al+base)   = __nv_bfloat162{l0,l1};
        *(__nv_bfloat162*)(Al+base+2) = __nv_bfloat162{l2,l3};
    }
    #pragma unroll
    for (int j = 0; j < 2; j++) {
        int idx = tid + 256*j;             // uint4 over 512
        int k = idx >> 3, c8 = idx & 7;
        *(uint4*)(Bh + k*72 + c8*8) = *(const uint4*)(g_WQh + k*64 + c8*8);
        *(uint4*)(Bl + k*72 + c8*8) = *(const uint4*)(g_WQl + k*64 + c8*8);
    }
    for (int l = tid; l < 1024; l += 256) { phiKs[l] = g_phiK[l]; Vs[l] = g_V[l]; }
    __syncthreads();

    // GEMM1: Q = H*WQ^T ; elu+1 elementwise on fragments ; -> Qs (phiQ fp32)
    {
        wmma::fragment<wmma::accumulator,16,16,16,float> fc[4];
        #pragma unroll
        for (int nt = 0; nt < 4; nt++) wmma::fill_fragment(fc[nt], 0.f);
        #pragma unroll
        for (int ks = 0; ks < 4; ks++) {
            wmma::fragment<wmma::matrix_a,16,16,16,__nv_bfloat16,wmma::row_major> fah, fal;
            wmma::load_matrix_sync(fah, Ah + (wid*16)*72 + ks*16, 72);
            wmma::load_matrix_sync(fal, Al + (wid*16)*72 + ks*16, 72);
            #pragma unroll
            for (int nt = 0; nt < 4; nt++) {
                wmma::fragment<wmma::matrix_b,16,16,16,__nv_bfloat16,wmma::row_major> fbh, fbl;
                wmma::load_matrix_sync(fbh, Bh + (ks*16)*72 + nt*16, 72);
                wmma::load_matrix_sync(fbl, Bl + (ks*16)*72 + nt*16, 72);
                wmma::mma_sync(fc[nt], fah, fbh, fc[nt]);
                wmma::mma_sync(fc[nt], fah, fbl, fc[nt]);
                wmma::mma_sync(fc[nt], fal, fbh, fc[nt]);
            }
        }
        #pragma unroll
        for (int nt = 0; nt < 4; nt++) {
            #pragma unroll
            for (int i = 0; i < fc[nt].num_elements; i++) {
                float q = fc[nt].x[i];
                fc[nt].x[i] = (q > 0.f) ? q + 1.f : expf(q);
            }
            wmma::store_matrix_sync(Qs + (wid*16)*68 + nt*16, fc[nt], 68, wmma::mem_row_major);
        }
    }
    __syncthreads();

    // split phiQ -> Ah/Al ; Bh/Bl <- KtV splits ; QK from Qs
    #pragma unroll
    for (int j = 0; j < 32; j++) {
        int idx = tid + 256*j;
        int r = idx >> 6, c = idx & 63;
        __nv_bfloat16 h, l; bf16_split(Qs[r*68 + c], h, l);
        Ah[r*72 + c] = h; Al[r*72 + c] = l;
    }
    #pragma unroll
    for (int j = 0; j < 2; j++) {
        int idx = tid + 256*j;
        int k = idx >> 3, c8 = idx & 7;
        *(uint4*)(Bh + k*72 + c8*8) = *(const uint4*)(g_KtVh + k*64 + c8*8);
        *(uint4*)(Bl + k*72 + c8*8) = *(const uint4*)(g_KtVl + k*64 + c8*8);
    }
    {
        int r = tid >> 1, mg = tid & 1;
        float s[8] = {};
        for (int e = 0; e < 64; e++) {
            float q = Qs[r*68 + e];
            #pragma unroll
            for (int mm = 0; mm < 8; mm++)
                s[mm] += q * phiKs[(mg*8 + mm)*64 + e];
        }
        #pragma unroll
        for (int mm = 0; mm < 8; mm++) QKs[r*20 + mg*8 + mm] = s[mm] * 0.125f;
    }
    __syncthreads();

    // softmax over M=16 per row
    if (tid < 128) {
        float mx = -1e30f;
        #pragma unroll
        for (int m = 0; m < 16; m++) mx = fmaxf(mx, QKs[tid*20 + m]);
        float ss = 0.f;
        #pragma unroll
        for (int m = 0; m < 16; m++) { float e_ = expf(QKs[tid*20 + m] - mx); QKs[tid*20 + m] = e_; ss += e_; }
        float inv = 1.f / ss;
        #pragma unroll
        for (int m = 0; m < 16; m++) QKs[tid*20 + m] *= inv;
    }
    __syncthreads();

    // mem_val -> mv (mean over t via atomic)
    {
        int r = tid >> 1, dq = tid & 1;
        int grow = row0 + r;
        int b_ = grow / (NT*NN);
        int n_ = grow & (NN - 1);
        float am[16];
        #pragma unroll
        for (int m = 0; m < 16; m++) am[m] = QKs[r*20 + m];
        float* mvp = g_mv + ((size_t)(b_*NN + n_))*64 + dq*32;
        #pragma unroll
        for (int dd = 0; dd < 32; dd++) {
            float s = 0.f;
            #pragma unroll
            for (int m = 0; m < 16; m++) s += am[m] * Vs[m*64 + dq*32 + dd];
            atomicAdd(mvp + dd, s * (1.f/NT));
        }
    }

    // GEMM2: main_att = phiQ*KtV -> Qs
    {
        wmma::fragment<wmma::accumulator,16,16,16,float> fc[4];
        #pragma unroll
        for (int nt = 0; nt < 4; nt++) wmma::fill_fragment(fc[nt], 0.f);
        #pragma unroll
        for (int ks = 0; ks < 4; ks++) {
            wmma::fragment<wmma::matrix_a,16,16,16,__nv_bfloat16,wmma::row_major> fah, fal;
            wmma::load_matrix_sync(fah, Ah + (wid*16)*72 + ks*16, 72);
            wmma::load_matrix_sync(fal, Al + (wid*16)*72 + ks*16, 72);
            #pragma unroll
            for (int nt = 0; nt < 4; nt++) {
                wmma::fragment<wmma::matrix_b,16,16,16,__nv_bfloat16,wmma::row_major> fbh, fbl;
                wmma::load_matrix_sync(fbh, Bh + (ks*16)*72 + nt*16, 72);
                wmma::load_matrix_sync(fbl, Bl + (ks*16)*72 + nt*16, 72);
                wmma::mma_sync(fc[nt], fah, fbh, fc[nt]);
                wmma::mma_sync(fc[nt], fah, fbl, fc[nt]);
                wmma::mma_sync(fc[nt], fal, fbh, fc[nt]);
            }
        }
        #pragma unroll
        for (int nt = 0; nt < 4; nt++)
            wmma::store_matrix_sync(Qs + (wid*16)*68 + nt*16, fc[nt], 68, wmma::mem_row_major);
    }
    __syncthreads();

    // Hp = main + H (H reloaded from gmem) ; split -> Ah/Al ; Bh/Bl <- outW^T
    #pragma unroll
    for (int j = 0; j < 32; j++) {
        int idx = tid + 256*j;
        int r = idx >> 6, c = idx & 63;
        float v = Qs[r*68 + c] + Hb[idx];
        __nv_bfloat16 h, l; bf16_split(v, h, l);
        Ah[r*72 + c] = h; Al[r*72 + c] = l;
    }
    #pragma unroll
    for (int j = 0; j < 2; j++) {
        int idx = tid + 256*j;
        int k = idx >> 3, c8 = idx & 7;
        *(uint4*)(Bh + k*72 + c8*8) = *(const uint4*)(g_oWh + k*64 + c8*8);
        *(uint4*)(Bl + k*72 + c8*8) = *(const uint4*)(g_oWl + k*64 + c8*8);
    }
    __syncthreads();

    // GEMM3: out = Hp*outW^T -> Qs
    {
        wmma::fragment<wmma::accumulator,16,16,16,float> fc[4];
        #pragma unroll
        for (int nt = 0; nt < 4; nt++) wmma::fill_fragment(fc[nt], 0.f);
        #pragma unroll
        for (int ks = 0; ks < 4; ks++) {
            wmma::fragment<wmma::matrix_a,16,16,16,__nv_bfloat16,wmma::row_major> fah, fal;
            wmma::load_matrix_sync(fah, Ah + (wid*16)*72 + ks*16, 72);
            wmma::load_matrix_sync(fal, Al + (wid*16)*72 + ks*16, 72);
            #pragma unroll
            for (int nt = 0; nt < 4; nt++) {
                wmma::fragment<wmma::matrix_b,16,16,16,__nv_bfloat16,wmma::row_major> fbh, fbl;
                wmma::load_matrix_sync(fbh, Bh + (ks*16)*72 + nt*16, 72);
                wmma::load_matrix_sync(fbl, Bl + (ks*16)*72 + nt*16, 72);
                wmma::mma_sync(fc[nt], fah, fbh, fc[nt]);
                wmma::mma_sync(fc[nt], fah, fbl, fc[nt]);
                wmma::mma_sync(fc[nt], fal, fbh, fc[nt]);
            }
        }
        #pragma unroll
        for (int nt = 0; nt < 4; nt++)
            wmma::store_matrix_sync(Qs + (wid*16)*68 + nt*16, fc[nt], 68, wmma::mem_row_major);
    }
    __syncthreads();

    // LN (2 threads/row via shfl) -> emit bf16 split of H'
    {
        int r = tid >> 1, half = tid & 1;
        float s = 0.f;
        #pragma unroll 8
        for (int c = 0; c < 32; c++) s += Qs[r*68 + half*32 + c] + outb[half*32 + c];
        s += __shfl_xor_sync(0xffffffffu, s, 1);
        float mu = s * (1.f/64.f);
        float v = 0.f;
        #pragma unroll 8
        for (int c = 0; c < 32; c++) {
            float d_ = Qs[r*68 + half*32 + c] + outb[half*32 + c] - mu;
            v += d_*d_;
        }
        v += __shfl_xor_sync(0xffffffffu, v, 1);
        if (half == 0) { rmean[r] = mu; rinv[r] = rsqrtf(v*(1.f/64.f) + 1e-5f); }
    }
    __syncthreads();
    #pragma unroll
    for (int j = 0; j < 32; j++) {
        int idx = tid + 256*j;
        int r = idx >> 6, c = idx & 63;
        float v = (Qs[r*68 + c] + outb[c] - rmean[r]) * rinv[r] * lng[c] + lnb[c];
        __nv_bfloat16 h, l; bf16_split(v, h, l);
        size_t go = (size_t)(row0 + r)*64 + c;
        g_Xh[0][go] = h; g_Xl[0][go] = l;
    }
}

// ====== A_dynamic logits via WMMA: S = mv.mv^T / 8, 128x128 tiles ==========
#define MVS_SMEM (4*128*72*2)   // 73728 B

__global__ void __launch_bounds__(256, 2)
k_mvS(float* __restrict__ Sout) {
    extern __shared__ __align__(16) __nv_bfloat16 smb[];
    __nv_bfloat16* Ah = smb;
    __nv_bfloat16* Al = Ah + 128*72;
    __nv_bfloat16* Bh = Al + 128*72;
    __nv_bfloat16* Bl = Bh + 128*72;
    int tid = threadIdx.x, wid = tid >> 5;
    int i0 = blockIdx.x*128, j0 = blockIdx.y*128, b = blockIdx.z;
    const __nv_bfloat16* mh = g_mvh + (size_t)b*NN*64;
    const __nv_bfloat16* ml = g_mvl + (size_t)b*NN*64;
    #pragma unroll
    for (int j = 0; j < 4; j++) {
        int idx = tid + 256*j;      // uint4 over 1024
        int r = idx >> 3, c8 = idx & 7;
        *(uint4*)(Ah + r*72 + c8*8) = *(const uint4*)(mh + (size_t)(i0+r)*64 + c8*8);
        *(uint4*)(Al + r*72 + c8*8) = *(const uint4*)(ml + (size_t)(i0+r)*64 + c8*8);
        *(uint4*)(Bh + r*72 + c8*8) = *(const uint4*)(mh + (size_t)(j0+r)*64 + c8*8);
        *(uint4*)(Bl + r*72 + c8*8) = *(const uint4*)(ml + (size_t)(j0+r)*64 + c8*8);
    }
    __syncthreads();
    wmma::fragment<wmma::accumulator,16,16,16,float> fc[8];
    #pragma unroll
    for (int nt = 0; nt < 8; nt++) wmma::fill_fragment(fc[nt], 0.f);
    #pragma unroll
    for (int ks = 0; ks < 4; ks++) {
        wmma::fragment<wmma::matrix_a,16,16,16,__nv_bfloat16,wmma::row_major> fah, fal;
        wmma::load_matrix_sync(fah, Ah + (wid*16)*72 + ks*16, 72);
        wmma::load_matrix_sync(fal, Al + (wid*16)*72 + ks*16, 72);
        #pragma unroll
        for (int nt = 0; nt < 8; nt++) {
            wmma::fragment<wmma::matrix_b,16,16,16,__nv_bfloat16,wmma::col_major> fbh, fbl;
            wmma::load_matrix_sync(fbh, Bh + (nt*16)*72 + ks*16, 72);
            wmma::load_matrix_sync(fbl, Bl + (nt*16)*72 + ks*16, 72);
            wmma::mma_sync(fc[nt], fah, fbh, fc[nt]);
            wmma::mma_sync(fc[nt], fah, fbl, fc[nt]);
            wmma::mma_sync(fc[nt], fal, fbh, fc[nt]);
        }
    }
    float* Sp = Sout + (size_t)b*NN*NN;
    #pragma unroll
    for (int nt = 0; nt < 8; nt++) {
        #pragma unroll
        for (int i = 0; i < fc[nt].num_elements; i++) fc[nt].x[i] *= 0.125f;
        wmma::store_matrix_sync(Sp + (size_t)(i0 + wid*16)*NN + j0 + nt*16, fc[nt], NN, wmma::mem_row_major);
    }
}

// -------- in-place softmax + fuse + bf16-split emit of A_fused -------------
// grid (NB, NN): consecutive CTAs share Ast row n (L2 reuse of Ast/dinv).
__global__ void k_softfuse(float* __restrict__ Adyn, float* __restrict__ Afus,
                           const float* __restrict__ Ast, const float* __restrict__ beta) {
    __shared__ float red[256];
    int b = blockIdx.x, n = blockIdx.y, t = threadIdx.x;
    float* Sr = Adyn + ((size_t)b*NN + n)*NN;
    float v[4];
    float mx = -1e30f;
    #pragma unroll
    for (int q = 0; q < 4; q++) { v[q] = Sr[t + q*256]; mx = fmaxf(mx, v[q]); }
    red[t] = mx; __syncthreads();
    for (int o = 128; o > 0; o >>= 1) { if (t < o) red[t] = fmaxf(red[t], red[t+o]); __syncthreads(); }
    mx = red[0]; __syncthreads();
    float s = 0.f;
    #pragma unroll
    for (int q = 0; q < 4; q++) { v[q] = expf(v[q] - mx); s += v[q]; }
    red[t] = s; __syncthreads();
    for (int o = 128; o > 0; o >>= 1) { if (t < o) red[t] += red[t+o]; __syncthreads(); }
    float inv = 1.f / red[0];
    float bta = fminf(fmaxf(beta[0], 0.f), 1.f);
    float din = g_dinv[n];
    float* Fr = Afus + ((size_t)b*NN + n)*NN;
    size_t arow = ((size_t)b*NN + n)*NN;
    #pragma unroll
    for (int q = 0; q < 4; q++) {
        int j = t + q*256;
        float p = v[q] * inv;
        Sr[j] = p;
        float f = bta*p + (1.f - bta) * din * g_dinv[j] * Ast[(size_t)n*NN + j];
        Fr[j] = f;
        __nv_bfloat16 h, l; bf16_split(f, h, l);
        g_Ah[arow + j] = h; g_Al[arow + j] = l;
    }
}

// ===== diffusion hop via WMMA bf16: 2 t-blocks/CTA + cp.async 2-stage ======
// stage layout (elems): Ah 128*72 | Al 128*72 | B0h,B0l,B1h,B1l 64*72 each
#define A_LD 72
#define DT_STAGE (2*128*A_LD + 4*64*A_LD)   // 36864 elems = 73728 B
#define DIFF_SMEM (2*DT_STAGE*2)            // 147456 B -> 1 CTA/SM

__global__ void __launch_bounds__(256)
k_diff_wmma(int hop) {
    extern __shared__ __align__(16) __nv_bfloat16 smb[];

    int tid = threadIdx.x;
    int wid = tid >> 5;

    int i0 = blockIdx.x * 128;
    int bt0 = blockIdx.y * 2;          // NT=12 even => both t in same batch
    int b  = bt0 / NT;
    const __nv_bfloat16* Ah_g = g_Ah + (size_t)b*NN*NN + (size_t)i0*NN;
    const __nv_bfloat16* Al_g = g_Al + (size_t)b*NN*NN + (size_t)i0*NN;
    const __nv_bfloat16* X0h = g_Xh[hop] + (size_t)bt0*NN*64;
    const __nv_bfloat16* X0l = g_Xl[hop] + (size_t)bt0*NN*64;
    const __nv_bfloat16* X1h = X0h + (size_t)NN*64;
    const __nv_bfloat16* X1l = X0l + (size_t)NN*64;

    // async loader for chunk kt into stage s
    auto load_stage = [&](int s, int kt) {
        __nv_bfloat16* st = smb + (size_t)s*DT_STAGE;
        __nv_bfloat16* Ahs = st;
        __nv_bfloat16* Als = st + 128*A_LD;
        __nv_bfloat16* B0hs = st + 2*128*A_LD;
        __nv_bfloat16* B0ls = B0hs + 64*A_LD;
        __nv_bfloat16* B1hs = B0ls + 64*A_LD;
        __nv_bfloat16* B1ls = B1hs + 64*A_LD;
        #pragma unroll
        for (int j = 0; j < 4; j++) {
            int idx = tid + 256*j;
            int r = idx >> 3, c8 = idx & 7;
            size_t go = (size_t)r*NN + kt*64 + c8*8;
            cp16((uint4*)Ahs + r*9 + c8, Ah_g + go);
            cp16((uint4*)Als + r*9 + c8, Al_g + go);
        }
        #pragma unroll
        for (int j = 0; j < 2; j++) {
            int idx = tid + 256*j;
            int k = idx >> 3, c8 = idx & 7;
            size_t go = (size_t)(kt*64 + k)*64 + c8*8;
            cp16((uint4*)B0hs + k*9 + c8, X0h + go);
            cp16((uint4*)B0ls + k*9 + c8, X0l + go);
            cp16((uint4*)B1hs + k*9 + c8, X1h + go);
            cp16((uint4*)B1ls + k*9 + c8, X1l + go);
        }
    };

    wmma::fragment<wmma::accumulator, 16, 16, 16, float> facc[2][4];
    #pragma unroll
    for (int tt = 0; tt < 2; tt++)
        #pragma unroll
        for (int nt = 0; nt < 4; nt++) wmma::fill_fragment(facc[tt][nt], 0.0f);

    load_stage(0, 0);
    CP_COMMIT();

    for (int kt = 0; kt < 16; kt++) {
        int cur = kt & 1;
        if (kt + 1 < 16) {
            load_stage(cur ^ 1, kt + 1);
            CP_COMMIT();
            CP_WAIT(1);
        } else {
            CP_WAIT(0);
        }
        __syncthreads();

        __nv_bfloat16* st = smb + (size_t)cur*DT_STAGE;
        __nv_bfloat16* Ahs = st;
        __nv_bfloat16* Als = st + 128*A_LD;
        __nv_bfloat16* B0hs = st + 2*128*A_LD;

        #pragma unroll
        for (int ks = 0; ks < 4; ks++) {
            wmma::fragment<wmma::matrix_a, 16, 16, 16, __nv_bfloat16, wmma::row_major> fah, fal;
            wmma::load_matrix_sync(fah, Ahs + (wid*16)*A_LD + ks*16, A_LD);
            wmma::load_matrix_sync(fal, Als + (wid*16)*A_LD + ks*16, A_LD);
            #pragma unroll
            for (int tt = 0; tt < 2; tt++) {
                const __nv_bfloat16* Bhp = B0hs + (2*tt)*64*A_LD;
                const __nv_bfloat16* Blp = B0hs + (2*tt + 1)*64*A_LD;
                #pragma unroll
                for (int nt = 0; nt < 4; nt++) {
                    wmma::fragment<wmma::matrix_b, 16, 16, 16, __nv_bfloat16, wmma::row_major> fbh, fbl;
                    wmma::load_matrix_sync(fbh, Bhp + (ks*16)*A_LD + nt*16, A_LD);
                    wmma::load_matrix_sync(fbl, Blp + (ks*16)*A_LD + nt*16, A_LD);
                    wmma::mma_sync(facc[tt][nt], fah, fbh, facc[tt][nt]);
                    wmma::mma_sync(facc[tt][nt], fah, fbl, facc[tt][nt]);
                    wmma::mma_sync(facc[tt][nt], fal, fbh, facc[tt][nt]);
                }
            }
        }
        __syncthreads();
    }

    // epilogue: per t-block, stage fp32 in aliased smem, split + write bf16
    float* Cs = (float*)smb;        // 128*68 fp32 = 34816 B
    #pragma unroll
    for (int tt = 0; tt < 2; tt++) {
        #pragma unroll
        for (int nt = 0; nt < 4; nt++)
            wmma::store_matrix_sync(Cs + (wid*16)*68 + nt*16, facc[tt][nt], 68, wmma::mem_row_major);
        __syncthreads();
        __nv_bfloat16* Oh_g = g_Xh[hop + 1] + (size_t)(bt0 + tt)*NN*64;
        __nv_bfloat16* Ol_g = g_Xl[hop + 1] + (size_t)(bt0 + tt)*NN*64;
        #pragma unroll
        for (int j = 0; j < 32; j++) {
            int idx = tid + 256*j;
            int r = idx >> 6, c = idx & 63;
            float v = Cs[r*68 + c];
            __nv_bfloat16 h, l; bf16_split(v, h, l);
            size_t go = (size_t)(i0 + r)*64 + c;
            Oh_g[go] = h; Ol_g[go] = l;
        }
        __syncthreads();
    }
}

// ====== projection via WMMA (K=192 in 3 chunks from bf16 splits) + LN ======
#define PROJ_SMEM ((2*128*A_LD + 2*64*A_LD) * 2)

__global__ void __launch_bounds__(256, 2)
k_proj(const float* __restrict__ pb,
       const float* __restrict__ lng, const float* __restrict__ lnb,
       float* __restrict__ Out) {
    extern __shared__ __align__(16) __nv_bfloat16 smb[];
    __nv_bfloat16* Ahs = smb;
    __nv_bfloat16* Als = Ahs + 128*A_LD;
    __nv_bfloat16* Bhs = Als + 128*A_LD;
    __nv_bfloat16* Bls = Bhs + 64*A_LD;

    int tid = threadIdx.x;
    int wid = tid >> 5;
    int row0 = blockIdx.x * 128;

    wmma::fragment<wmma::accumulator, 16, 16, 16, float> facc[4];
    #pragma unroll
    for (int nt = 0; nt < 4; nt++) wmma::fill_fragment(facc[nt], 0.0f);

    #pragma unroll
    for (int kt = 0; kt < 3; kt++) {
        const __nv_bfloat16* Sh = g_Xh[kt];
        const __nv_bfloat16* Sl = g_Xl[kt];
        #pragma unroll
        for (int j = 0; j < 4; j++) {
            int idx = tid + 256*j;
            int r = idx >> 3, c8 = idx & 7;
            size_t go = (size_t)(row0 + r)*64 + c8*8;
            ((uint4*)Ahs)[r*9 + c8] = *(const uint4*)(Sh + go);
            ((uint4*)Als)[r*9 + c8] = *(const uint4*)(Sl + go);
        }
        #pragma unroll
        for (int j = 0; j < 2; j++) {
            int idx = tid + 256*j;
            int k = idx >> 3, c8 = idx & 7;
            size_t go = (size_t)kt*4096 + (size_t)k*64 + c8*8;
            ((uint4*)Bhs)[k*9 + c8] = *(const uint4*)(g_pWh + go);
            ((uint4*)Bls)[k*9 + c8] = *(const uint4*)(g_pWl + go);
        }
        __syncthreads();

        #pragma unroll
        for (int ks = 0; ks < 4; ks++) {
            wmma::fragment<wmma::matrix_a, 16, 16, 16, __nv_bfloat16, wmma::row_major> fah, fal;
            wmma::load_matrix_sync(fah, Ahs + (wid*16)*A_LD + ks*16, A_LD);
            wmma::load_matrix_sync(fal, Als + (wid*16)*A_LD + ks*16, A_LD);
            #pragma unroll
            for (int nt = 0; nt < 4; nt++) {
                wmma::fragment<wmma::matrix_b, 16, 16, 16, __nv_bfloat16, wmma::row_major> fbh, fbl;
                wmma::load_matrix_sync(fbh, Bhs + (ks*16)*A_LD + nt*16, A_LD);
                wmma::load_matrix_sync(fbl, Bls + (ks*16)*A_LD + nt*16, A_LD);
                wmma::mma_sync(facc[nt], fah, fbh, facc[nt]);
                wmma::mma_sync(facc[nt], fah, fbl, facc[nt]);
                wmma::mma_sync(facc[nt], fal, fbh, facc[nt]);
            }
        }
        __syncthreads();
    }

    float* Cs = (float*)smb;
    float* rmean = Cs + 128*68;
    float* rinv  = rmean + 128;
    #pragma unroll
    for (int nt = 0; nt < 4; nt++)
        wmma::store_matrix_sync(Cs + (wid*16)*68 + nt*16, facc[nt], 68, wmma::mem_row_major);
    __syncthreads();
    {
        int r = tid >> 1, half = tid & 1;
        float s = 0.f;
        #pragma unroll 8
        for (int c = 0; c < 32; c++) s += Cs[r*68 + half*32 + c] + pb[half*32 + c];
        s += __shfl_xor_sync(0xffffffffu, s, 1);
        float mu = s * (1.f/64.f);
        float v = 0.f;
        #pragma unroll 8
        for (int c = 0; c < 32; c++) {
            float d_ = Cs[r*68 + half*32 + c] + pb[half*32 + c] - mu;
            v += d_*d_;
        }
        v += __shfl_xor_sync(0xffffffffu, v, 1);
        if (half == 0) { rmean[r] = mu; rinv[r] = rsqrtf(v*(1.f/64.f) + 1e-5f); }
    }
    __syncthreads();
    #pragma unroll
    for (int j = 0; j < 32; j++) {
        int idx = tid + 256*j;
        int r = idx >> 6, c = idx & 63;
        float v = (Cs[r*68 + c] + pb[c] - rmean[r]) * rinv[r] * lng[c] + lnb[c];
        Out[(size_t)(row0 + r)*64 + c] = v;
    }
}

// ---------------- launch ----------------------------------------------------
extern "C" void kernel_launch(void* const* d_in, const int* in_sizes, int n_in,
                              void* d_out, int out_size) {
    const float* H    = (const float*)d_in[0];
    const float* Ast  = (const float*)d_in[1];
    const float* WQ   = (const float*)d_in[2];
    const float* WK   = (const float*)d_in[3];
    const float* WV   = (const float*)d_in[4];
    const float* PHI  = (const float*)d_in[5];
    const float* outW = (const float*)d_in[6];
    const float* outb = (const float*)d_in[7];
    const float* smag = (const float*)d_in[8];
    const float* smab = (const float*)d_in[9];
    const float* beta = (const float*)d_in[10];
    const float* pW   = (const float*)d_in[11];
    const float* pb   = (const float*)d_in[12];
    const float* agg  = (const float*)d_in[13];
    const float* agb  = (const float*)d_in[14];

    float* out  = (float*)d_out;
    float* Hsp  = out;                                    // [B,T,N,D]
    float* Adyn = out + (size_t)ROWS_TOT*64;              // [B,N,N]
    float* Afus = Adyn + (size_t)NB*NN*NN;                // [B,N,N]

    cudaFuncSetAttribute(k_attn, cudaFuncAttributeMaxDynamicSharedMemorySize, ATTN_SMEM);
    cudaFuncSetAttribute(k_mvS, cudaFuncAttributeMaxDynamicSharedMemorySize, MVS_SMEM);
    cudaFuncSetAttribute(k_diff_wmma, cudaFuncAttributeMaxDynamicSharedMemorySize, DIFF_SMEM);
    cudaFuncSetAttribute(k_proj, cudaFuncAttributeMaxDynamicSharedMemorySize, PROJ_SMEM);

    k_pre<<<1, 256>>>(PHI, WK, WV, WQ, outW, pW);
    k_deg<<<NN, 256>>>(Ast);
    k_zero<<<(NB*NN*ND + 255)/256, 256>>>();
    k_attn<<<ROWS_TOT/128, 256, ATTN_SMEM>>>(H, outb, smag, smab);
    k_splitmv<<<NB*NN*ND/4/256, 256>>>();
    dim3 gS(8, 8, NB);
    k_mvS<<<gS, 256, MVS_SMEM>>>(Adyn);
    dim3 gF(NB, NN);
    k_softfuse<<<gF, 256>>>(Adyn, Afus, Ast, beta);
    dim3 gD(8, NB*NT/2);
    k_diff_wmma<<<gD, 256, DIFF_SMEM>>>(0);
    k_diff_wmma<<<gD, 256, DIFF_SMEM>>>(1);
    k_proj<<<ROWS_TOT/128, 256, PROJ_SMEM>>>(pb, agg, agb, Hsp);
}